// round 1
// baseline (speedup 1.0000x reference)
#include <cuda_runtime.h>
#include <math.h>

// Problem constants
#define BB   2
#define SS   2048
#define HH   16
#define DD   128
#define HID  2048
#define MROWS 4096          // B*S
#define KDIM  2048
#define N1    6144          // 3*HID
#define N2    2048
#define SCALE 0.08838834764831843f

// Scratch (allocation-free: __device__ globals)
__device__ float g_q[BB*HH*SS*DD];
__device__ float g_k[BB*HH*SS*DD];
__device__ float g_v[BB*HH*SS*DD];
__device__ float g_attn[(size_t)MROWS*HID];

// ---------------------------------------------------------------------------
// SGEMM: C[m,n] = sum_k A[m,k] * W[n,k]   (A row-major MxK, W row-major NxK)
// 128x128 tile, BK=8, 256 threads, 8x8 per thread.
// MODE 0: scatter qkv -> g_q/g_k/g_v in (B,H,S,D) layout
// MODE 1: A is g_attn, write C = d_out
// ---------------------------------------------------------------------------
template<int MODE>
__global__ __launch_bounds__(256) void sgemm_kernel(const float* __restrict__ A,
                                                    const float* __restrict__ W,
                                                    float* __restrict__ C) {
    __shared__ float As[8][128];
    __shared__ float Bs[8][128];

    const float* Aarr = (MODE == 0) ? A : g_attn;

    float acc[8][8];
#pragma unroll
    for (int i = 0; i < 8; ++i)
#pragma unroll
        for (int j = 0; j < 8; ++j) acc[i][j] = 0.f;

    int tid = threadIdx.x;
    int tx = tid & 15;          // 0..15 -> n sub-block
    int ty = tid >> 4;          // 0..15 -> m sub-block
    int lrow = tid >> 1;        // 0..127 loader row
    int lk   = (tid & 1) * 4;   // 0 or 4

    const float* Aptr = Aarr + (size_t)(blockIdx.y * 128 + lrow) * KDIM + lk;
    const float* Wptr = W    + (size_t)(blockIdx.x * 128 + lrow) * KDIM + lk;

    for (int k0 = 0; k0 < KDIM; k0 += 8) {
        float4 av = *(const float4*)(Aptr + k0);
        float4 wv = *(const float4*)(Wptr + k0);
        __syncthreads();
        As[lk + 0][lrow] = av.x; As[lk + 1][lrow] = av.y;
        As[lk + 2][lrow] = av.z; As[lk + 3][lrow] = av.w;
        Bs[lk + 0][lrow] = wv.x; Bs[lk + 1][lrow] = wv.y;
        Bs[lk + 2][lrow] = wv.z; Bs[lk + 3][lrow] = wv.w;
        __syncthreads();
#pragma unroll
        for (int kk = 0; kk < 8; ++kk) {
            float ar[8], br[8];
#pragma unroll
            for (int i = 0; i < 8; ++i) ar[i] = As[kk][ty * 8 + i];
#pragma unroll
            for (int j = 0; j < 8; ++j) br[j] = Bs[kk][tx * 8 + j];
#pragma unroll
            for (int i = 0; i < 8; ++i)
#pragma unroll
                for (int j = 0; j < 8; ++j)
                    acc[i][j] += ar[i] * br[j];
        }
    }

    int mbase = blockIdx.y * 128 + ty * 8;
    int nbase = blockIdx.x * 128 + tx * 8;
#pragma unroll
    for (int i = 0; i < 8; ++i) {
        int m = mbase + i;
#pragma unroll
        for (int j = 0; j < 8; ++j) {
            int n = nbase + j;
            float v = acc[i][j];
            if (MODE == 0) {
                int qkvi = n >> 11;        // 0:q 1:k 2:v
                int rem  = n & 2047;
                int h = rem >> 7;
                int d = rem & 127;
                int b = m >> 11;
                int s = m & 2047;
                float* dst = (qkvi == 0) ? g_q : ((qkvi == 1) ? g_k : g_v);
                dst[(((size_t)(b * HH + h)) * SS + s) * DD + d] = v;
            } else {
                C[(size_t)m * N2 + n] = v;
            }
        }
    }
}

// ---------------------------------------------------------------------------
// RoPE in-place on g_q, g_k. One thread per (row, d<64) pair.
// ---------------------------------------------------------------------------
__global__ __launch_bounds__(256) void rope_kernel() {
    int idx = blockIdx.x * 256 + threadIdx.x;   // < B*H*S*64
    int d   = idx & 63;
    int row = idx >> 6;
    int s   = row & (SS - 1);

    // inv_freq = 10000^{-d/64}; log(10000)/64 = 0.14391156831212787
    float inv = expf(-(float)d * 0.14391156831212787f);
    float ang = (float)s * inv;
    float c, sn;
    sincosf(ang, &sn, &c);

    size_t base = (size_t)row * DD;
    float q0 = g_q[base + d], q1 = g_q[base + d + 64];
    g_q[base + d]      = q0 * c - q1 * sn;
    g_q[base + d + 64] = q1 * c + q0 * sn;
    float k0 = g_k[base + d], k1 = g_k[base + d + 64];
    g_k[base + d]      = k0 * c - k1 * sn;
    g_k[base + d + 64] = k1 * c + k0 * sn;
}

// ---------------------------------------------------------------------------
// Flash attention, fp32, causal.
// Block = 256 threads handles a 64-row q tile for one (b,h).
// Thread layout: r = tid>>2 (q row 0..63), ql = tid&3 (covers 32 d-cols and
// 16 interleaved k-cols c = ql + 4*j).
// Shared strides chosen for conflict-free float4 access (132 = 128+4).
// ---------------------------------------------------------------------------
#define QSTR 132
#define PSTR 65
#define FL_SMEM_FLOATS (3 * 64 * QSTR + 64 * PSTR)
#define FL_SMEM_BYTES  (FL_SMEM_FLOATS * 4)

__global__ __launch_bounds__(256) void flash_kernel() {
    extern __shared__ float sm[];
    float* Qs = sm;
    float* Ks = sm + 64 * QSTR;
    float* Vs = sm + 2 * 64 * QSTR;
    float* Ps = sm + 3 * 64 * QSTR;

    int tid = threadIdx.x;
    int bh  = blockIdx.y;
    int qt  = (int)gridDim.x - 1 - (int)blockIdx.x;   // heavy tiles first

    const float* Qg = g_q + (size_t)bh * (SS * DD);
    const float* Kg = g_k + (size_t)bh * (SS * DD);
    const float* Vg = g_v + (size_t)bh * (SS * DD);

    int q0 = qt * 64;
    // load Q tile (64 x 128)
    for (int i = tid; i < 64 * 32; i += 256) {
        int r  = i >> 5;
        int c4 = (i & 31) << 2;
        *(float4*)&Qs[r * QSTR + c4] =
            *(const float4*)(Qg + (size_t)(q0 + r) * DD + c4);
    }

    int r  = tid >> 2;
    int ql = tid & 3;
    int qglob = q0 + r;

    float m = -1e30f, l = 0.f;
    float acc[32];
#pragma unroll
    for (int i = 0; i < 32; ++i) acc[i] = 0.f;

    int ntiles = qt + 1;
    for (int jt = 0; jt < ntiles; ++jt) {
        int kbase = jt * 64;
        __syncthreads();
        for (int i = tid; i < 64 * 32; i += 256) {
            int rr = i >> 5;
            int c4 = (i & 31) << 2;
            *(float4*)&Ks[rr * QSTR + c4] =
                *(const float4*)(Kg + (size_t)(kbase + rr) * DD + c4);
            *(float4*)&Vs[rr * QSTR + c4] =
                *(const float4*)(Vg + (size_t)(kbase + rr) * DD + c4);
        }
        __syncthreads();

        // scores: 16 interleaved k columns c = ql + 4*j
        float sreg[16];
#pragma unroll
        for (int j = 0; j < 16; ++j) sreg[j] = 0.f;
#pragma unroll 4
        for (int d4 = 0; d4 < 128; d4 += 4) {
            float4 qv = *(const float4*)&Qs[r * QSTR + d4];
#pragma unroll
            for (int j = 0; j < 16; ++j) {
                float4 kv = *(const float4*)&Ks[(ql + 4 * j) * QSTR + d4];
                sreg[j] += qv.x * kv.x + qv.y * kv.y + qv.z * kv.z + qv.w * kv.w;
            }
        }

        // causal mask + running max
        float tmax = -1e30f;
#pragma unroll
        for (int j = 0; j < 16; ++j) {
            int kg = kbase + ql + 4 * j;
            sreg[j] = (kg <= qglob) ? sreg[j] * SCALE : -1e30f;
            tmax = fmaxf(tmax, sreg[j]);
        }
        tmax = fmaxf(tmax, __shfl_xor_sync(0xffffffffu, tmax, 1));
        tmax = fmaxf(tmax, __shfl_xor_sync(0xffffffffu, tmax, 2));
        float mnew = fmaxf(m, tmax);

        float psum = 0.f;
#pragma unroll
        for (int j = 0; j < 16; ++j) {
            float p = __expf(sreg[j] - mnew);
            psum += p;
            Ps[r * PSTR + ql + 4 * j] = p;
        }
        psum += __shfl_xor_sync(0xffffffffu, psum, 1);
        psum += __shfl_xor_sync(0xffffffffu, psum, 2);

        float alpha = __expf(m - mnew);
        l = l * alpha + psum;
        m = mnew;
#pragma unroll
        for (int i = 0; i < 32; ++i) acc[i] *= alpha;
        __syncwarp();

        // PV: acc[dc] += sum_c Ps[r][c] * Vs[c][ql*32 + dc]
        const float* vbase = Vs + ql * 32;
        const float* prow  = Ps + r * PSTR;
#pragma unroll 2
        for (int c = 0; c < 64; ++c) {
            float p = prow[c];
            const float* vr = vbase + c * QSTR;
#pragma unroll
            for (int jj = 0; jj < 8; ++jj) {
                int j8 = (jj + 2 * ql) & 7;   // stagger banks across ql
                float4 vv = *(const float4*)(vr + j8 * 4);
                acc[j8 * 4 + 0] += p * vv.x;
                acc[j8 * 4 + 1] += p * vv.y;
                acc[j8 * 4 + 2] += p * vv.z;
                acc[j8 * 4 + 3] += p * vv.w;
            }
        }
    }

    // epilogue -> g_attn in (b, s, h*D+d) layout for GEMM2
    float invl = 1.f / l;
    int b = bh >> 4, h = bh & 15;
    float* orow = g_attn + ((size_t)(b * SS + qglob)) * HID + h * DD + ql * 32;
#pragma unroll
    for (int jj = 0; jj < 8; ++jj) {
        float4 o;
        o.x = acc[jj * 4 + 0] * invl;
        o.y = acc[jj * 4 + 1] * invl;
        o.z = acc[jj * 4 + 2] * invl;
        o.w = acc[jj * 4 + 3] * invl;
        *(float4*)(orow + jj * 4) = o;
    }
}

// ---------------------------------------------------------------------------
extern "C" void kernel_launch(void* const* d_in, const int* in_sizes, int n_in,
                              void* d_out, int out_size) {
    const float* x     = (const float*)d_in[0];
    const float* w_qkv = (const float*)d_in[1];
    const float* w_o   = (const float*)d_in[2];
    float* out = (float*)d_out;

    // 1. QKV projection -> g_q/g_k/g_v (B,H,S,D)
    dim3 g1(N1 / 128, MROWS / 128);
    sgemm_kernel<0><<<g1, 256>>>(x, w_qkv, nullptr);

    // 2. RoPE in-place on q,k
    int rope_threads = BB * HH * SS * 64;
    rope_kernel<<<rope_threads / 256, 256>>>();

    // 3. Flash attention -> g_attn (B,S,HID)
    cudaFuncSetAttribute(flash_kernel,
                         cudaFuncAttributeMaxDynamicSharedMemorySize,
                         FL_SMEM_BYTES);
    flash_kernel<<<dim3(SS / 64, BB * HH), 256, FL_SMEM_BYTES>>>();

    // 4. Output projection -> d_out
    dim3 g2(N2 / 128, MROWS / 128);
    sgemm_kernel<1><<<g2, 256>>>(nullptr, w_o, out);
}

// round 2
// speedup vs baseline: 4.6311x; 4.6311x over previous
#include <cuda_runtime.h>
#include <math.h>

// Problem constants
#define BB   2
#define SS   2048
#define HH   16
#define DD   128
#define HID  2048
#define MROWS 4096          // B*S
#define KDIM  2048
#define N1    6144          // 3*HID
#define N2    2048
#define SCALE 0.08838834764831843f

// Scratch (allocation-free: __device__ globals)
__device__ float g_q[BB*HH*SS*DD];
__device__ float g_k[BB*HH*SS*DD];
__device__ float g_v[BB*HH*SS*DD];
__device__ float g_attn[(size_t)MROWS*HID];

// ---------------------------------------------------------------------------
// SGEMM: C[m,n] = sum_k A[m,k] * W[n,k]   (A row-major MxK, W row-major NxK)
// 128x128 tile, BK=8, 256 threads, 8x8 per thread.
// MODE 0: scatter qkv -> g_q/g_k/g_v in (B,H,S,D) layout
// MODE 1: A is g_attn, write C = d_out
// ---------------------------------------------------------------------------
template<int MODE>
__global__ __launch_bounds__(256) void sgemm_kernel(const float* __restrict__ A,
                                                    const float* __restrict__ W,
                                                    float* __restrict__ C) {
    __shared__ float As[8][128];
    __shared__ float Bs[8][128];

    const float* Aarr = (MODE == 0) ? A : g_attn;

    float acc[8][8];
#pragma unroll
    for (int i = 0; i < 8; ++i)
#pragma unroll
        for (int j = 0; j < 8; ++j) acc[i][j] = 0.f;

    int tid = threadIdx.x;
    int tx = tid & 15;          // 0..15 -> n sub-block
    int ty = tid >> 4;          // 0..15 -> m sub-block
    int lrow = tid >> 1;        // 0..127 loader row
    int lk   = (tid & 1) * 4;   // 0 or 4

    const float* Aptr = Aarr + (size_t)(blockIdx.y * 128 + lrow) * KDIM + lk;
    const float* Wptr = W    + (size_t)(blockIdx.x * 128 + lrow) * KDIM + lk;

    for (int k0 = 0; k0 < KDIM; k0 += 8) {
        float4 av = *(const float4*)(Aptr + k0);
        float4 wv = *(const float4*)(Wptr + k0);
        __syncthreads();
        As[lk + 0][lrow] = av.x; As[lk + 1][lrow] = av.y;
        As[lk + 2][lrow] = av.z; As[lk + 3][lrow] = av.w;
        Bs[lk + 0][lrow] = wv.x; Bs[lk + 1][lrow] = wv.y;
        Bs[lk + 2][lrow] = wv.z; Bs[lk + 3][lrow] = wv.w;
        __syncthreads();
#pragma unroll
        for (int kk = 0; kk < 8; ++kk) {
            float ar[8], br[8];
#pragma unroll
            for (int i = 0; i < 8; ++i) ar[i] = As[kk][ty * 8 + i];
#pragma unroll
            for (int j = 0; j < 8; ++j) br[j] = Bs[kk][tx * 8 + j];
#pragma unroll
            for (int i = 0; i < 8; ++i)
#pragma unroll
                for (int j = 0; j < 8; ++j)
                    acc[i][j] += ar[i] * br[j];
        }
    }

    int mbase = blockIdx.y * 128 + ty * 8;
    int nbase = blockIdx.x * 128 + tx * 8;
#pragma unroll
    for (int i = 0; i < 8; ++i) {
        int m = mbase + i;
#pragma unroll
        for (int j = 0; j < 8; ++j) {
            int n = nbase + j;
            float v = acc[i][j];
            if (MODE == 0) {
                int qkvi = n >> 11;        // 0:q 1:k 2:v
                int rem  = n & 2047;
                int h = rem >> 7;
                int d = rem & 127;
                int b = m >> 11;
                int s = m & 2047;
                float* dst = (qkvi == 0) ? g_q : ((qkvi == 1) ? g_k : g_v);
                dst[(((size_t)(b * HH + h)) * SS + s) * DD + d] = v;
            } else {
                C[(size_t)m * N2 + n] = v;
            }
        }
    }
}

// ---------------------------------------------------------------------------
// RoPE in-place on g_q, g_k. One thread per (row, d<64) pair.
// ---------------------------------------------------------------------------
__global__ __launch_bounds__(256) void rope_kernel() {
    int idx = blockIdx.x * 256 + threadIdx.x;   // < B*H*S*64
    int d   = idx & 63;
    int row = idx >> 6;
    int s   = row & (SS - 1);

    float inv = expf(-(float)d * 0.14391156831212787f);
    float ang = (float)s * inv;
    float c, sn;
    sincosf(ang, &sn, &c);

    size_t base = (size_t)row * DD;
    float q0 = g_q[base + d], q1 = g_q[base + d + 64];
    g_q[base + d]      = q0 * c - q1 * sn;
    g_q[base + d + 64] = q1 * c + q0 * sn;
    float k0 = g_k[base + d], k1 = g_k[base + d + 64];
    g_k[base + d]      = k0 * c - k1 * sn;
    g_k[base + d + 64] = k1 * c + k0 * sn;
}

// ---------------------------------------------------------------------------
// Flash attention, fp32, causal — register-blocked GEMM formulation.
// Block = 256 threads (16x16), 64-row q tile, 64-col k tiles.
//   Stage A (S = Q K^T): each thread owns a 4x4 S block.
//     Qs, Ks stored d-major [d][row] so inner loop over d reads 2 float4s.
//   Softmax: in registers, 16-lane shuffle reductions across tx.
//   Stage B (O += P V): P stored transposed [c][r]; each thread owns 4x8 of O.
// ---------------------------------------------------------------------------
#define QK_STR 68    // stride for Qs/Ks/PsT (64 + 4 pad)
#define V_STR  132   // stride for Vs (128 + 4 pad)
#define FL2_SMEM_FLOATS (128*QK_STR /*Qs*/ + 128*QK_STR /*Ks*/ + 64*V_STR /*Vs*/ + 64*QK_STR /*PsT*/)
#define FL2_SMEM_BYTES  (FL2_SMEM_FLOATS * 4)

__global__ __launch_bounds__(256) void flash_kernel() {
    extern __shared__ float sm[];
    float* Qs  = sm;                          // [128][QK_STR]  (d-major)
    float* Ks  = Qs  + 128 * QK_STR;          // [128][QK_STR]  (d-major)
    float* Vs  = Ks  + 128 * QK_STR;          // [64][V_STR]    (row-major)
    float* PsT = Vs  + 64 * V_STR;            // [64][QK_STR]   (c-major)

    int tid = threadIdx.x;
    int tx  = tid & 15;
    int ty  = tid >> 4;
    int bh  = blockIdx.y;
    int qt  = (int)gridDim.x - 1 - (int)blockIdx.x;   // heavy tiles first
    int q0  = qt * 64;

    const float* Qg = g_q + (size_t)bh * (SS * DD);
    const float* Kg = g_k + (size_t)bh * (SS * DD);
    const float* Vg = g_v + (size_t)bh * (SS * DD);

    // Load Q tile transposed: Qs[d][r]
    for (int i = tid; i < 64 * 32; i += 256) {
        int r  = i >> 5;
        int c4 = (i & 31) << 2;
        float4 v = *(const float4*)(Qg + (size_t)(q0 + r) * DD + c4);
        Qs[(c4 + 0) * QK_STR + r] = v.x;
        Qs[(c4 + 1) * QK_STR + r] = v.y;
        Qs[(c4 + 2) * QK_STR + r] = v.z;
        Qs[(c4 + 3) * QK_STR + r] = v.w;
    }

    float m[4], l[4], acc[4][8];
#pragma unroll
    for (int i = 0; i < 4; ++i) { m[i] = -1e30f; l[i] = 0.f; }
#pragma unroll
    for (int i = 0; i < 4; ++i)
#pragma unroll
        for (int j = 0; j < 8; ++j) acc[i][j] = 0.f;

    int ntiles = qt + 1;
    for (int jt = 0; jt < ntiles; ++jt) {
        int kbase = jt * 64;
        __syncthreads();   // prev PV reads of Vs / loads done
        // K tile transposed: Ks[d][c]; V tile natural: Vs[c][d]
        for (int i = tid; i < 64 * 32; i += 256) {
            int rr = i >> 5;
            int c4 = (i & 31) << 2;
            float4 kv = *(const float4*)(Kg + (size_t)(kbase + rr) * DD + c4);
            Ks[(c4 + 0) * QK_STR + rr] = kv.x;
            Ks[(c4 + 1) * QK_STR + rr] = kv.y;
            Ks[(c4 + 2) * QK_STR + rr] = kv.z;
            Ks[(c4 + 3) * QK_STR + rr] = kv.w;
            *(float4*)&Vs[rr * V_STR + c4] =
                *(const float4*)(Vg + (size_t)(kbase + rr) * DD + c4);
        }
        __syncthreads();

        // --- S = Q K^T : 4x4 per thread ---
        float s[4][4];
#pragma unroll
        for (int i = 0; i < 4; ++i)
#pragma unroll
            for (int j = 0; j < 4; ++j) s[i][j] = 0.f;

#pragma unroll 8
        for (int d = 0; d < 128; ++d) {
            float4 qv = *(const float4*)&Qs[d * QK_STR + ty * 4];
            float4 kv = *(const float4*)&Ks[d * QK_STR + tx * 4];
            float qa[4] = {qv.x, qv.y, qv.z, qv.w};
            float ka[4] = {kv.x, kv.y, kv.z, kv.w};
#pragma unroll
            for (int i = 0; i < 4; ++i)
#pragma unroll
                for (int j = 0; j < 4; ++j)
                    s[i][j] += qa[i] * ka[j];
        }

        // --- mask + online softmax (registers + 16-lane shuffles) ---
        bool diag = (jt == qt);
#pragma unroll
        for (int i = 0; i < 4; ++i) {
            int qglob = q0 + ty * 4 + i;
            float tmax = -1e30f;
#pragma unroll
            for (int j = 0; j < 4; ++j) {
                float v = s[i][j] * SCALE;
                if (diag && (kbase + tx * 4 + j > qglob)) v = -1e30f;
                s[i][j] = v;
                tmax = fmaxf(tmax, v);
            }
            tmax = fmaxf(tmax, __shfl_xor_sync(0xffffffffu, tmax, 1));
            tmax = fmaxf(tmax, __shfl_xor_sync(0xffffffffu, tmax, 2));
            tmax = fmaxf(tmax, __shfl_xor_sync(0xffffffffu, tmax, 4));
            tmax = fmaxf(tmax, __shfl_xor_sync(0xffffffffu, tmax, 8));
            float mnew = fmaxf(m[i], tmax);
            float psum = 0.f;
#pragma unroll
            for (int j = 0; j < 4; ++j) {
                float p = __expf(s[i][j] - mnew);
                s[i][j] = p;
                psum += p;
            }
            psum += __shfl_xor_sync(0xffffffffu, psum, 1);
            psum += __shfl_xor_sync(0xffffffffu, psum, 2);
            psum += __shfl_xor_sync(0xffffffffu, psum, 4);
            psum += __shfl_xor_sync(0xffffffffu, psum, 8);
            float alpha = __expf(m[i] - mnew);
            l[i] = l[i] * alpha + psum;
            m[i] = mnew;
#pragma unroll
            for (int j = 0; j < 8; ++j) acc[i][j] *= alpha;
        }

        // write P transposed: PsT[c][r]
#pragma unroll
        for (int j = 0; j < 4; ++j)
#pragma unroll
            for (int i = 0; i < 4; ++i)
                PsT[(tx * 4 + j) * QK_STR + ty * 4 + i] = s[i][j];
        __syncthreads();

        // --- O += P V : 4x8 per thread ---
#pragma unroll 4
        for (int c = 0; c < 64; ++c) {
            float4 pv = *(const float4*)&PsT[c * QK_STR + ty * 4];
            float4 v0 = *(const float4*)&Vs[c * V_STR + tx * 8];
            float4 v1 = *(const float4*)&Vs[c * V_STR + tx * 8 + 4];
            float pa[4] = {pv.x, pv.y, pv.z, pv.w};
            float va[8] = {v0.x, v0.y, v0.z, v0.w, v1.x, v1.y, v1.z, v1.w};
#pragma unroll
            for (int i = 0; i < 4; ++i)
#pragma unroll
                for (int j = 0; j < 8; ++j)
                    acc[i][j] += pa[i] * va[j];
        }
    }

    // epilogue -> g_attn (b, s, h*D+d)
    int b = bh >> 4, h = bh & 15;
#pragma unroll
    for (int i = 0; i < 4; ++i) {
        float invl = 1.f / l[i];
        int row = q0 + ty * 4 + i;
        float* orow = g_attn + ((size_t)(b * SS + row)) * HID + h * DD + tx * 8;
        float4 o0, o1;
        o0.x = acc[i][0] * invl; o0.y = acc[i][1] * invl;
        o0.z = acc[i][2] * invl; o0.w = acc[i][3] * invl;
        o1.x = acc[i][4] * invl; o1.y = acc[i][5] * invl;
        o1.z = acc[i][6] * invl; o1.w = acc[i][7] * invl;
        *(float4*)(orow)     = o0;
        *(float4*)(orow + 4) = o1;
    }
}

// ---------------------------------------------------------------------------
extern "C" void kernel_launch(void* const* d_in, const int* in_sizes, int n_in,
                              void* d_out, int out_size) {
    const float* x     = (const float*)d_in[0];
    const float* w_qkv = (const float*)d_in[1];
    const float* w_o   = (const float*)d_in[2];
    float* out = (float*)d_out;

    // 1. QKV projection -> g_q/g_k/g_v (B,H,S,D)
    dim3 g1(N1 / 128, MROWS / 128);
    sgemm_kernel<0><<<g1, 256>>>(x, w_qkv, nullptr);

    // 2. RoPE in-place on q,k
    int rope_threads = BB * HH * SS * 64;
    rope_kernel<<<rope_threads / 256, 256>>>();

    // 3. Flash attention -> g_attn (B,S,HID)
    cudaFuncSetAttribute(flash_kernel,
                         cudaFuncAttributeMaxDynamicSharedMemorySize,
                         FL2_SMEM_BYTES);
    flash_kernel<<<dim3(SS / 64, BB * HH), 256, FL2_SMEM_BYTES>>>();

    // 4. Output projection -> d_out
    dim3 g2(N2 / 128, MROWS / 128);
    sgemm_kernel<1><<<g2, 256>>>(nullptr, w_o, out);
}

// round 6
// speedup vs baseline: 8.9291x; 1.9281x over previous
#include <cuda_runtime.h>
#include <cstdint>
#include <math.h>

// Problem constants
#define BB   2
#define SS   2048
#define HH   16
#define DD   128
#define HID  2048
#define MROWS 4096          // B*S
#define KDIM  2048
#define N1    6144          // 3*HID
#define N2    2048
#define SCALE 0.08838834764831843f

// Scratch (allocation-free: __device__ globals)
__device__ float g_q[BB*HH*SS*DD];
__device__ float g_k[BB*HH*SS*DD];
__device__ float g_v[BB*HH*SS*DD];
__device__ float g_attn[(size_t)MROWS*HID];

// ---------------------------------------------------------------------------
// Helpers
// ---------------------------------------------------------------------------
__device__ __forceinline__ uint32_t smem_u32(const void* p) {
    uint32_t a;
    asm("{ .reg .u64 t; cvta.to.shared.u64 t, %1; cvt.u32.u64 %0, t; }"
        : "=r"(a) : "l"(p));
    return a;
}
__device__ __forceinline__ void cp_async16(uint32_t dst, const void* src) {
    asm volatile("cp.async.cg.shared.global [%0], [%1], 16;" :: "r"(dst), "l"(src));
}
__device__ __forceinline__ uint32_t f2tf(float f) {
    uint32_t u;
    asm("cvt.rna.tf32.f32 %0, %1;" : "=r"(u) : "f"(f));
    return u;
}
// D += A*B : m16n8k8 tf32 (row.col)
__device__ __forceinline__ void mma_tf32(float* d, const uint32_t* a, const uint32_t* b) {
    asm volatile(
        "mma.sync.aligned.m16n8k8.row.col.f32.tf32.tf32.f32 "
        "{%0,%1,%2,%3}, {%4,%5,%6,%7}, {%8,%9}, {%0,%1,%2,%3};"
        : "+f"(d[0]), "+f"(d[1]), "+f"(d[2]), "+f"(d[3])
        : "r"(a[0]), "r"(a[1]), "r"(a[2]), "r"(a[3]), "r"(b[0]), "r"(b[1]));
}

// ---------------------------------------------------------------------------
// tf32 mma.sync GEMM: C[m,n] = sum_k A[m,k] * W[n,k]
// CTA tile 128x128, K-chunk 32, 256 threads (8 warps: 4 m x 2 n).
// Warp tile 32x64 = 2 x 8 fragments (m16n8k8). 2-stage cp.async pipeline.
// smem layout: [row][k] with stride 36 floats (conflict-free fragment loads).
// MODE 0: A = x, scatter qkv -> g_q/g_k/g_v (B,H,S,D)
// MODE 1: A = g_attn, C = d_out
// ---------------------------------------------------------------------------
#define MT 128
#define NT 128
#define KC 32
#define ASTR 36
#define STG_FLOATS (MT*ASTR + NT*ASTR)        // 9216 floats per stage
#define GEMM_SMEM  (2 * STG_FLOATS * 4)       // 73728 bytes
#define NCHUNK (KDIM / KC)                    // 64

template<int MODE>
__global__ __launch_bounds__(256) void mma_gemm(const float* __restrict__ Ain,
                                                const float* __restrict__ W,
                                                float* __restrict__ C) {
    extern __shared__ float sm[];
    uint32_t sb = smem_u32(sm);
    int tid = threadIdx.x;
    int wid = tid >> 5;
    int lid = tid & 31;
    int g   = lid >> 2;     // 0..7
    int tq  = lid & 3;      // 0..3

    const float* A = (MODE == 0) ? Ain : g_attn;
    int m0 = blockIdx.y * MT;
    int n0 = blockIdx.x * NT;

    int wm = (wid & 3) * 32;     // warp m base within tile
    int wn = (wid >> 2) * 64;    // warp n base within tile

    float acc[2][8][4];
#pragma unroll
    for (int i = 0; i < 2; ++i)
#pragma unroll
        for (int j = 0; j < 8; ++j)
#pragma unroll
            for (int q = 0; q < 4; ++q) acc[i][j][q] = 0.f;

    // loader: stage buffer stg, K offset k0
    auto load_stage = [&](int stg, int k0) {
        uint32_t abase = sb + stg * STG_FLOATS * 4;
        uint32_t bbase = abase + MT * ASTR * 4;
#pragma unroll
        for (int j = 0; j < 4; ++j) {            // A: 1024 16B chunks
            int ci = tid + j * 256;
            int r = ci >> 3, kc = ci & 7;
            cp_async16(abase + (r * ASTR + kc * 4) * 4,
                       A + (size_t)(m0 + r) * KDIM + k0 + kc * 4);
        }
#pragma unroll
        for (int j = 0; j < 4; ++j) {            // B: 1024 16B chunks
            int ci = tid + j * 256;
            int r = ci >> 3, kc = ci & 7;
            cp_async16(bbase + (r * ASTR + kc * 4) * 4,
                       W + (size_t)(n0 + r) * KDIM + k0 + kc * 4);
        }
    };

    load_stage(0, 0);
    asm volatile("cp.async.commit_group;" ::: "memory");

    for (int u = 0; u < NCHUNK; ++u) {
        if (u + 1 < NCHUNK) {
            load_stage((u + 1) & 1, (u + 1) * KC);
            asm volatile("cp.async.commit_group;" ::: "memory");
            asm volatile("cp.async.wait_group 1;" ::: "memory");
        } else {
            asm volatile("cp.async.wait_group 0;" ::: "memory");
        }
        __syncthreads();

        const float* As = sm + (u & 1) * STG_FLOATS;
        const float* Bs = As + MT * ASTR;

#pragma unroll
        for (int ks = 0; ks < KC; ks += 8) {
            uint32_t af[2][4], bf[8][2];
#pragma unroll
            for (int im = 0; im < 2; ++im) {
                int row = wm + im * 16 + g;
                af[im][0] = f2tf(As[row * ASTR + ks + tq]);
                af[im][1] = f2tf(As[(row + 8) * ASTR + ks + tq]);
                af[im][2] = f2tf(As[row * ASTR + ks + tq + 4]);
                af[im][3] = f2tf(As[(row + 8) * ASTR + ks + tq + 4]);
            }
#pragma unroll
            for (int in_ = 0; in_ < 8; ++in_) {
                int col = wn + in_ * 8 + g;
                bf[in_][0] = f2tf(Bs[col * ASTR + ks + tq]);
                bf[in_][1] = f2tf(Bs[col * ASTR + ks + tq + 4]);
            }
#pragma unroll
            for (int im = 0; im < 2; ++im)
#pragma unroll
                for (int in_ = 0; in_ < 8; ++in_)
                    mma_tf32(acc[im][in_], af[im], bf[in_]);
        }
        __syncthreads();
    }

    // ---- epilogue ----
    // thread holds: rows (wm+im*16+g, +8), cols (wn+in_*8+tq*2, +1)
#pragma unroll
    for (int im = 0; im < 2; ++im) {
#pragma unroll
        for (int half = 0; half < 2; ++half) {
            int m = m0 + wm + im * 16 + g + half * 8;
            float* dstrow;
            if (MODE == 0) {
                int qkvi = n0 >> 11;
                int rem  = n0 & 2047;
                int h = rem >> 7;
                int b = m >> 11, s = m & 2047;
                float* dst = (qkvi == 0) ? g_q : ((qkvi == 1) ? g_k : g_v);
                dstrow = dst + (((size_t)(b * HH + h)) * SS + s) * DD;   // + d
            } else {
                dstrow = C + (size_t)m * N2 + n0;
            }
#pragma unroll
            for (int in_ = 0; in_ < 8; ++in_) {
                int dcol = wn + in_ * 8 + tq * 2;   // local col (also d for MODE 0)
                float2 v;
                v.x = acc[im][in_][half * 2 + 0];
                v.y = acc[im][in_][half * 2 + 1];
                *(float2*)(dstrow + dcol) = v;
            }
        }
    }
}

// ---------------------------------------------------------------------------
// RoPE in-place on g_q, g_k.
// ---------------------------------------------------------------------------
__global__ __launch_bounds__(256) void rope_kernel() {
    int idx = blockIdx.x * 256 + threadIdx.x;
    int d   = idx & 63;
    int row = idx >> 6;
    int s   = row & (SS - 1);

    float inv = expf(-(float)d * 0.14391156831212787f);
    float ang = (float)s * inv;
    float c, sn;
    sincosf(ang, &sn, &c);

    size_t base = (size_t)row * DD;
    float q0 = g_q[base + d], q1 = g_q[base + d + 64];
    g_q[base + d]      = q0 * c - q1 * sn;
    g_q[base + d + 64] = q1 * c + q0 * sn;
    float k0 = g_k[base + d], k1 = g_k[base + d + 64];
    g_k[base + d]      = k0 * c - k1 * sn;
    g_k[base + d + 64] = k1 * c + k0 * sn;
}

// ---------------------------------------------------------------------------
// Flash attention, fp32, causal — register-blocked (R2, unchanged).
// ---------------------------------------------------------------------------
#define QK_STR 68
#define V_STR  132
#define FL2_SMEM_FLOATS (128*QK_STR + 128*QK_STR + 64*V_STR + 64*QK_STR)
#define FL2_SMEM_BYTES  (FL2_SMEM_FLOATS * 4)

__global__ __launch_bounds__(256) void flash_kernel() {
    extern __shared__ float sm[];
    float* Qs  = sm;
    float* Ks  = Qs  + 128 * QK_STR;
    float* Vs  = Ks  + 128 * QK_STR;
    float* PsT = Vs  + 64 * V_STR;

    int tid = threadIdx.x;
    int tx  = tid & 15;
    int ty  = tid >> 4;
    int bh  = blockIdx.y;
    int qt  = (int)gridDim.x - 1 - (int)blockIdx.x;
    int q0  = qt * 64;

    const float* Qg = g_q + (size_t)bh * (SS * DD);
    const float* Kg = g_k + (size_t)bh * (SS * DD);
    const float* Vg = g_v + (size_t)bh * (SS * DD);

    for (int i = tid; i < 64 * 32; i += 256) {
        int r  = i >> 5;
        int c4 = (i & 31) << 2;
        float4 v = *(const float4*)(Qg + (size_t)(q0 + r) * DD + c4);
        Qs[(c4 + 0) * QK_STR + r] = v.x;
        Qs[(c4 + 1) * QK_STR + r] = v.y;
        Qs[(c4 + 2) * QK_STR + r] = v.z;
        Qs[(c4 + 3) * QK_STR + r] = v.w;
    }

    float m[4], l[4], acc[4][8];
#pragma unroll
    for (int i = 0; i < 4; ++i) { m[i] = -1e30f; l[i] = 0.f; }
#pragma unroll
    for (int i = 0; i < 4; ++i)
#pragma unroll
        for (int j = 0; j < 8; ++j) acc[i][j] = 0.f;

    int ntiles = qt + 1;
    for (int jt = 0; jt < ntiles; ++jt) {
        int kbase = jt * 64;
        __syncthreads();
        for (int i = tid; i < 64 * 32; i += 256) {
            int rr = i >> 5;
            int c4 = (i & 31) << 2;
            float4 kv = *(const float4*)(Kg + (size_t)(kbase + rr) * DD + c4);
            Ks[(c4 + 0) * QK_STR + rr] = kv.x;
            Ks[(c4 + 1) * QK_STR + rr] = kv.y;
            Ks[(c4 + 2) * QK_STR + rr] = kv.z;
            Ks[(c4 + 3) * QK_STR + rr] = kv.w;
            *(float4*)&Vs[rr * V_STR + c4] =
                *(const float4*)(Vg + (size_t)(kbase + rr) * DD + c4);
        }
        __syncthreads();

        float s[4][4];
#pragma unroll
        for (int i = 0; i < 4; ++i)
#pragma unroll
            for (int j = 0; j < 4; ++j) s[i][j] = 0.f;

#pragma unroll 8
        for (int d = 0; d < 128; ++d) {
            float4 qv = *(const float4*)&Qs[d * QK_STR + ty * 4];
            float4 kv = *(const float4*)&Ks[d * QK_STR + tx * 4];
            float qa[4] = {qv.x, qv.y, qv.z, qv.w};
            float ka[4] = {kv.x, kv.y, kv.z, kv.w};
#pragma unroll
            for (int i = 0; i < 4; ++i)
#pragma unroll
                for (int j = 0; j < 4; ++j)
                    s[i][j] += qa[i] * ka[j];
        }

        bool diag = (jt == qt);
#pragma unroll
        for (int i = 0; i < 4; ++i) {
            int qglob = q0 + ty * 4 + i;
            float tmax = -1e30f;
#pragma unroll
            for (int j = 0; j < 4; ++j) {
                float v = s[i][j] * SCALE;
                if (diag && (kbase + tx * 4 + j > qglob)) v = -1e30f;
                s[i][j] = v;
                tmax = fmaxf(tmax, v);
            }
            tmax = fmaxf(tmax, __shfl_xor_sync(0xffffffffu, tmax, 1));
            tmax = fmaxf(tmax, __shfl_xor_sync(0xffffffffu, tmax, 2));
            tmax = fmaxf(tmax, __shfl_xor_sync(0xffffffffu, tmax, 4));
            tmax = fmaxf(tmax, __shfl_xor_sync(0xffffffffu, tmax, 8));
            float mnew = fmaxf(m[i], tmax);
            float psum = 0.f;
#pragma unroll
            for (int j = 0; j < 4; ++j) {
                float p = __expf(s[i][j] - mnew);
                s[i][j] = p;
                psum += p;
            }
            psum += __shfl_xor_sync(0xffffffffu, psum, 1);
            psum += __shfl_xor_sync(0xffffffffu, psum, 2);
            psum += __shfl_xor_sync(0xffffffffu, psum, 4);
            psum += __shfl_xor_sync(0xffffffffu, psum, 8);
            float alpha = __expf(m[i] - mnew);
            l[i] = l[i] * alpha + psum;
            m[i] = mnew;
#pragma unroll
            for (int j = 0; j < 8; ++j) acc[i][j] *= alpha;
        }

#pragma unroll
        for (int j = 0; j < 4; ++j)
#pragma unroll
            for (int i = 0; i < 4; ++i)
                PsT[(tx * 4 + j) * QK_STR + ty * 4 + i] = s[i][j];
        __syncthreads();

#pragma unroll 4
        for (int c = 0; c < 64; ++c) {
            float4 pv = *(const float4*)&PsT[c * QK_STR + ty * 4];
            float4 v0 = *(const float4*)&Vs[c * V_STR + tx * 8];
            float4 v1 = *(const float4*)&Vs[c * V_STR + tx * 8 + 4];
            float pa[4] = {pv.x, pv.y, pv.z, pv.w};
            float va[8] = {v0.x, v0.y, v0.z, v0.w, v1.x, v1.y, v1.z, v1.w};
#pragma unroll
            for (int i = 0; i < 4; ++i)
#pragma unroll
                for (int j = 0; j < 8; ++j)
                    acc[i][j] += pa[i] * va[j];
        }
    }

    int b = bh >> 4, h = bh & 15;
#pragma unroll
    for (int i = 0; i < 4; ++i) {
        float invl = 1.f / l[i];
        int row = q0 + ty * 4 + i;
        float* orow = g_attn + ((size_t)(b * SS + row)) * HID + h * DD + tx * 8;
        float4 o0, o1;
        o0.x = acc[i][0] * invl; o0.y = acc[i][1] * invl;
        o0.z = acc[i][2] * invl; o0.w = acc[i][3] * invl;
        o1.x = acc[i][4] * invl; o1.y = acc[i][5] * invl;
        o1.z = acc[i][6] * invl; o1.w = acc[i][7] * invl;
        *(float4*)(orow)     = o0;
        *(float4*)(orow + 4) = o1;
    }
}

// ---------------------------------------------------------------------------
extern "C" void kernel_launch(void* const* d_in, const int* in_sizes, int n_in,
                              void* d_out, int out_size) {
    const float* x     = (const float*)d_in[0];
    const float* w_qkv = (const float*)d_in[1];
    const float* w_o   = (const float*)d_in[2];
    float* out = (float*)d_out;

    cudaFuncSetAttribute(mma_gemm<0>, cudaFuncAttributeMaxDynamicSharedMemorySize,
                         GEMM_SMEM);
    cudaFuncSetAttribute(mma_gemm<1>, cudaFuncAttributeMaxDynamicSharedMemorySize,
                         GEMM_SMEM);
    cudaFuncSetAttribute(flash_kernel, cudaFuncAttributeMaxDynamicSharedMemorySize,
                         FL2_SMEM_BYTES);

    // 1. QKV projection (tf32 mma.sync) -> g_q/g_k/g_v (B,H,S,D)
    dim3 g1(N1 / NT, MROWS / MT);
    mma_gemm<0><<<g1, 256, GEMM_SMEM>>>(x, w_qkv, nullptr);

    // 2. RoPE in-place on q,k
    rope_kernel<<<(BB * HH * SS * 64) / 256, 256>>>();

    // 3. Flash attention -> g_attn (B,S,HID)
    flash_kernel<<<dim3(SS / 64, BB * HH), 256, FL2_SMEM_BYTES>>>();

    // 4. Output projection (tf32 mma.sync) -> d_out
    dim3 g2(N2 / NT, MROWS / MT);
    mma_gemm<1><<<g2, 256, GEMM_SMEM>>>(nullptr, w_o, out);
}

// round 7
// speedup vs baseline: 17.3421x; 1.9422x over previous
#include <cuda_runtime.h>
#include <cstdint>
#include <math.h>

// Problem constants
#define BB   2
#define SS   2048
#define HH   16
#define DD   128
#define HID  2048
#define MROWS 4096          // B*S
#define KDIM  2048
#define N1    6144          // 3*HID
#define N2    2048
#define SCALE 0.08838834764831843f

// Scratch (allocation-free: __device__ globals)
__device__ float g_q[BB*HH*SS*DD];
__device__ float g_k[BB*HH*SS*DD];
__device__ float g_v[BB*HH*SS*DD];
__device__ float g_attn[(size_t)MROWS*HID];

// ---------------------------------------------------------------------------
// Helpers
// ---------------------------------------------------------------------------
__device__ __forceinline__ void cp_async16(uint32_t dst, const void* src) {
    asm volatile("cp.async.cg.shared.global [%0], [%1], 16;" :: "r"(dst), "l"(src));
}
__device__ __forceinline__ uint32_t smem_u32(const void* p) {
    uint32_t a;
    asm("{ .reg .u64 t; cvta.to.shared.u64 t, %1; cvt.u32.u64 %0, t; }"
        : "=r"(a) : "l"(p));
    return a;
}
__device__ __forceinline__ uint32_t f2tf(float f) {
    uint32_t u;
    asm("cvt.rna.tf32.f32 %0, %1;" : "=r"(u) : "f"(f));
    return u;
}
__device__ __forceinline__ float tfround(float f) { return __uint_as_float(f2tf(f)); }

// D += A*B : m16n8k8 tf32 (row.col)
__device__ __forceinline__ void mma_tf32(float* d, const uint32_t* a, const uint32_t* b) {
    asm volatile(
        "mma.sync.aligned.m16n8k8.row.col.f32.tf32.tf32.f32 "
        "{%0,%1,%2,%3}, {%4,%5,%6,%7}, {%8,%9}, {%0,%1,%2,%3};"
        : "+f"(d[0]), "+f"(d[1]), "+f"(d[2]), "+f"(d[3])
        : "r"(a[0]), "r"(a[1]), "r"(a[2]), "r"(a[3]), "r"(b[0]), "r"(b[1]));
}

// ---------------------------------------------------------------------------
// tf32 mma.sync GEMM (R6, unchanged except V rounding in MODE 0 epilogue)
// ---------------------------------------------------------------------------
#define MT 128
#define NT 128
#define KC 32
#define ASTR 36
#define STG_FLOATS (MT*ASTR + NT*ASTR)
#define GEMM_SMEM  (2 * STG_FLOATS * 4)
#define NCHUNK (KDIM / KC)

template<int MODE>
__global__ __launch_bounds__(256) void mma_gemm(const float* __restrict__ Ain,
                                                const float* __restrict__ W,
                                                float* __restrict__ C) {
    extern __shared__ float sm[];
    uint32_t sb = smem_u32(sm);
    int tid = threadIdx.x;
    int wid = tid >> 5;
    int lid = tid & 31;
    int g   = lid >> 2;
    int tq  = lid & 3;

    const float* A = (MODE == 0) ? Ain : g_attn;
    int m0 = blockIdx.y * MT;
    int n0 = blockIdx.x * NT;

    int wm = (wid & 3) * 32;
    int wn = (wid >> 2) * 64;

    float acc[2][8][4];
#pragma unroll
    for (int i = 0; i < 2; ++i)
#pragma unroll
        for (int j = 0; j < 8; ++j)
#pragma unroll
            for (int q = 0; q < 4; ++q) acc[i][j][q] = 0.f;

    auto load_stage = [&](int stg, int k0) {
        uint32_t abase = sb + stg * STG_FLOATS * 4;
        uint32_t bbase = abase + MT * ASTR * 4;
#pragma unroll
        for (int j = 0; j < 4; ++j) {
            int ci = tid + j * 256;
            int r = ci >> 3, kc = ci & 7;
            cp_async16(abase + (r * ASTR + kc * 4) * 4,
                       A + (size_t)(m0 + r) * KDIM + k0 + kc * 4);
        }
#pragma unroll
        for (int j = 0; j < 4; ++j) {
            int ci = tid + j * 256;
            int r = ci >> 3, kc = ci & 7;
            cp_async16(bbase + (r * ASTR + kc * 4) * 4,
                       W + (size_t)(n0 + r) * KDIM + k0 + kc * 4);
        }
    };

    load_stage(0, 0);
    asm volatile("cp.async.commit_group;" ::: "memory");

    for (int u = 0; u < NCHUNK; ++u) {
        if (u + 1 < NCHUNK) {
            load_stage((u + 1) & 1, (u + 1) * KC);
            asm volatile("cp.async.commit_group;" ::: "memory");
            asm volatile("cp.async.wait_group 1;" ::: "memory");
        } else {
            asm volatile("cp.async.wait_group 0;" ::: "memory");
        }
        __syncthreads();

        const float* As = sm + (u & 1) * STG_FLOATS;
        const float* Bs = As + MT * ASTR;

#pragma unroll
        for (int ks = 0; ks < KC; ks += 8) {
            uint32_t af[2][4], bf[8][2];
#pragma unroll
            for (int im = 0; im < 2; ++im) {
                int row = wm + im * 16 + g;
                af[im][0] = f2tf(As[row * ASTR + ks + tq]);
                af[im][1] = f2tf(As[(row + 8) * ASTR + ks + tq]);
                af[im][2] = f2tf(As[row * ASTR + ks + tq + 4]);
                af[im][3] = f2tf(As[(row + 8) * ASTR + ks + tq + 4]);
            }
#pragma unroll
            for (int in_ = 0; in_ < 8; ++in_) {
                int col = wn + in_ * 8 + g;
                bf[in_][0] = f2tf(Bs[col * ASTR + ks + tq]);
                bf[in_][1] = f2tf(Bs[col * ASTR + ks + tq + 4]);
            }
#pragma unroll
            for (int im = 0; im < 2; ++im)
#pragma unroll
                for (int in_ = 0; in_ < 8; ++in_)
                    mma_tf32(acc[im][in_], af[im], bf[in_]);
        }
        __syncthreads();
    }

#pragma unroll
    for (int im = 0; im < 2; ++im) {
#pragma unroll
        for (int half = 0; half < 2; ++half) {
            int m = m0 + wm + im * 16 + g + half * 8;
            float* dstrow;
            bool rnd = false;
            if (MODE == 0) {
                int qkvi = n0 >> 11;
                int rem  = n0 & 2047;
                int h = rem >> 7;
                int b = m >> 11, s = m & 2047;
                float* dst = (qkvi == 0) ? g_q : ((qkvi == 1) ? g_k : g_v);
                rnd = (qkvi == 2);     // pre-round V to tf32 for flash mma
                dstrow = dst + (((size_t)(b * HH + h)) * SS + s) * DD;
            } else {
                dstrow = C + (size_t)m * N2 + n0;
            }
#pragma unroll
            for (int in_ = 0; in_ < 8; ++in_) {
                int dcol = wn + in_ * 8 + tq * 2;
                float2 v;
                v.x = acc[im][in_][half * 2 + 0];
                v.y = acc[im][in_][half * 2 + 1];
                if (rnd) { v.x = tfround(v.x); v.y = tfround(v.y); }
                *(float2*)(dstrow + dcol) = v;
            }
        }
    }
}

// ---------------------------------------------------------------------------
// RoPE in-place on g_q, g_k; stores tf32-rounded (exact under mma truncation).
// ---------------------------------------------------------------------------
__global__ __launch_bounds__(256) void rope_kernel() {
    int idx = blockIdx.x * 256 + threadIdx.x;
    int d   = idx & 63;
    int row = idx >> 6;
    int s   = row & (SS - 1);

    float inv = expf(-(float)d * 0.14391156831212787f);
    float ang = (float)s * inv;
    float c, sn;
    sincosf(ang, &sn, &c);

    size_t base = (size_t)row * DD;
    float q0 = g_q[base + d], q1 = g_q[base + d + 64];
    g_q[base + d]      = tfround(q0 * c - q1 * sn);
    g_q[base + d + 64] = tfround(q1 * c + q0 * sn);
    float k0 = g_k[base + d], k1 = g_k[base + d + 64];
    g_k[base + d]      = tfround(k0 * c - k1 * sn);
    g_k[base + d + 64] = tfround(k1 * c + k0 * sn);
}

// ---------------------------------------------------------------------------
// Flash attention v3 — tf32 mma.sync for QK^T and PV.
// CTA: 256 thr (8 warps), q-tile 128 (warp = 16 rows), k-tile 64.
// smem (floats): Qs[128][132] | Ks 2x[64][132] | Vs[64][136] | Ps[128][68]
// All fragment loads bank-conflict-free by stride choice.
// K double-buffered, V prefetched under QK via cp.async.
// ---------------------------------------------------------------------------
#define FQSTR 132
#define FKSTR 132
#define FVSTR 136
#define FPSTR 68
#define FQ_OFF 0
#define FK_OFF (128*FQSTR)                       // 16896
#define FK_BUF (64*FKSTR)                        // 8448
#define FV_OFF (FK_OFF + 2*FK_BUF)               // 33792
#define FP_OFF (FV_OFF + 64*FVSTR)               // 42496
#define FL3_FLOATS (FP_OFF + 128*FPSTR)          // 51200
#define FL3_SMEM_BYTES (FL3_FLOATS * 4)          // 204800

__global__ __launch_bounds__(256) void flash_kernel() {
    extern __shared__ float sm[];
    uint32_t sb = smem_u32(sm);
    const uint32_t* smu = (const uint32_t*)sm;

    int tid = threadIdx.x;
    int wid = tid >> 5;
    int lid = tid & 31;
    int g   = lid >> 2;
    int tq  = lid & 3;
    int wm  = wid * 16;              // warp's q-row base within tile

    int bh = blockIdx.y;
    int qt = 15 - (int)blockIdx.x;   // heavy tiles first
    int q0 = qt * 128;
    int ntiles = 2 * qt + 2;

    const float* Qg = g_q + (size_t)bh * (SS * DD);
    const float* Kg = g_k + (size_t)bh * (SS * DD);
    const float* Vg = g_v + (size_t)bh * (SS * DD);

    // ---- prologue: Q tile (128x128) + K tile 0 -> one cp.async group
#pragma unroll
    for (int j = 0; j < 16; ++j) {
        int ci = tid + j * 256;          // 4096 chunks
        int r = ci >> 5, kc = ci & 31;
        cp_async16(sb + (FQ_OFF + r * FQSTR + kc * 4) * 4,
                   Qg + (size_t)(q0 + r) * DD + kc * 4);
    }
#pragma unroll
    for (int j = 0; j < 8; ++j) {
        int ci = tid + j * 256;          // 2048 chunks
        int r = ci >> 5, kc = ci & 31;
        cp_async16(sb + (FK_OFF + r * FKSTR + kc * 4) * 4,
                   Kg + (size_t)r * DD + kc * 4);
    }
    asm volatile("cp.async.commit_group;" ::: "memory");

    int r0 = q0 + wm + g;
    int r1 = r0 + 8;

    float mx0 = -1e30f, mx1 = -1e30f, l0 = 0.f, l1 = 0.f;
    float o[16][4];
#pragma unroll
    for (int f = 0; f < 16; ++f)
#pragma unroll
        for (int q = 0; q < 4; ++q) o[f][q] = 0.f;

    for (int jt = 0; jt < ntiles; ++jt) {
        int kbase = jt * 64;
        bool haveNext = (jt + 1 < ntiles);
        if (jt > 0) __syncthreads();     // Vs free (PV jt-1 done), K buf free

        // prefetch V[jt] and K[jt+1]
#pragma unroll
        for (int j = 0; j < 8; ++j) {
            int ci = tid + j * 256;
            int r = ci >> 5, kc = ci & 31;
            cp_async16(sb + (FV_OFF + r * FVSTR + kc * 4) * 4,
                       Vg + (size_t)(kbase + r) * DD + kc * 4);
        }
        asm volatile("cp.async.commit_group;" ::: "memory");
        if (haveNext) {
            int nb = (jt + 1) & 1;
#pragma unroll
            for (int j = 0; j < 8; ++j) {
                int ci = tid + j * 256;
                int r = ci >> 5, kc = ci & 31;
                cp_async16(sb + (FK_OFF + nb * FK_BUF + r * FKSTR + kc * 4) * 4,
                           Kg + (size_t)(kbase + 64 + r) * DD + kc * 4);
            }
            asm volatile("cp.async.commit_group;" ::: "memory");
            asm volatile("cp.async.wait_group 2;" ::: "memory");  // K[jt] done
        } else {
            asm volatile("cp.async.wait_group 1;" ::: "memory");  // K[jt] done
        }
        __syncthreads();

        // ---- S = Q K^T  (warp: 16 x 64, 8 nfrags, k = 128)
        const uint32_t* Ku = smu + FK_OFF + (jt & 1) * FK_BUF;
        float s[8][4];
#pragma unroll
        for (int f = 0; f < 8; ++f)
#pragma unroll
            for (int q = 0; q < 4; ++q) s[f][q] = 0.f;

#pragma unroll
        for (int ks = 0; ks < 128; ks += 8) {
            uint32_t af[4];
            af[0] = smu[FQ_OFF + (wm + g) * FQSTR + ks + tq];
            af[1] = smu[FQ_OFF + (wm + 8 + g) * FQSTR + ks + tq];
            af[2] = smu[FQ_OFF + (wm + g) * FQSTR + ks + tq + 4];
            af[3] = smu[FQ_OFF + (wm + 8 + g) * FQSTR + ks + tq + 4];
#pragma unroll
            for (int f = 0; f < 8; ++f) {
                uint32_t bf[2];
                bf[0] = Ku[(f * 8 + g) * FKSTR + ks + tq];
                bf[1] = Ku[(f * 8 + g) * FKSTR + ks + tq + 4];
                mma_tf32(s[f], af, bf);
            }
        }

        // wait V[jt]
        if (haveNext) asm volatile("cp.async.wait_group 1;" ::: "memory");
        else          asm volatile("cp.async.wait_group 0;" ::: "memory");
        __syncthreads();

        // ---- online softmax (registers + 4-lane shuffles)
        bool diag = (jt >= 2 * qt);
        float tm0 = -1e30f, tm1 = -1e30f;
#pragma unroll
        for (int f = 0; f < 8; ++f) {
            float v0 = s[f][0] * SCALE, v1 = s[f][1] * SCALE;
            float v2 = s[f][2] * SCALE, v3 = s[f][3] * SCALE;
            if (diag) {
                int c0 = kbase + f * 8 + 2 * tq, c1 = c0 + 1;
                if (c0 > r0) v0 = -1e30f;
                if (c1 > r0) v1 = -1e30f;
                if (c0 > r1) v2 = -1e30f;
                if (c1 > r1) v3 = -1e30f;
            }
            s[f][0] = v0; s[f][1] = v1; s[f][2] = v2; s[f][3] = v3;
            tm0 = fmaxf(tm0, fmaxf(v0, v1));
            tm1 = fmaxf(tm1, fmaxf(v2, v3));
        }
        tm0 = fmaxf(tm0, __shfl_xor_sync(0xffffffffu, tm0, 1));
        tm0 = fmaxf(tm0, __shfl_xor_sync(0xffffffffu, tm0, 2));
        tm1 = fmaxf(tm1, __shfl_xor_sync(0xffffffffu, tm1, 1));
        tm1 = fmaxf(tm1, __shfl_xor_sync(0xffffffffu, tm1, 2));
        float mn0 = fmaxf(mx0, tm0), mn1 = fmaxf(mx1, tm1);

        float ps0 = 0.f, ps1 = 0.f;
#pragma unroll
        for (int f = 0; f < 8; ++f) {
            float p0 = tfround(__expf(s[f][0] - mn0));
            float p1 = tfround(__expf(s[f][1] - mn0));
            float p2 = tfround(__expf(s[f][2] - mn1));
            float p3 = tfround(__expf(s[f][3] - mn1));
            ps0 += p0 + p1;
            ps1 += p2 + p3;
            int c = f * 8 + 2 * tq;
            *(float2*)&sm[FP_OFF + (wm + g) * FPSTR + c]     = make_float2(p0, p1);
            *(float2*)&sm[FP_OFF + (wm + 8 + g) * FPSTR + c] = make_float2(p2, p3);
        }
        ps0 += __shfl_xor_sync(0xffffffffu, ps0, 1);
        ps0 += __shfl_xor_sync(0xffffffffu, ps0, 2);
        ps1 += __shfl_xor_sync(0xffffffffu, ps1, 1);
        ps1 += __shfl_xor_sync(0xffffffffu, ps1, 2);

        float a0 = __expf(mx0 - mn0), a1 = __expf(mx1 - mn1);
        l0 = l0 * a0 + ps0;
        l1 = l1 * a1 + ps1;
        mx0 = mn0; mx1 = mn1;
#pragma unroll
        for (int f = 0; f < 16; ++f) {
            o[f][0] *= a0; o[f][1] *= a0;
            o[f][2] *= a1; o[f][3] *= a1;
        }
        __syncthreads();   // Ps visible to whole warp... (whole CTA row-groups are warp-local, but V shared)

        // ---- O += P V  (warp: 16 x 128, 16 nfrags, k = 64)
#pragma unroll
        for (int ks = 0; ks < 64; ks += 8) {
            uint32_t af[4];
            af[0] = smu[FP_OFF + (wm + g) * FPSTR + ks + tq];
            af[1] = smu[FP_OFF + (wm + 8 + g) * FPSTR + ks + tq];
            af[2] = smu[FP_OFF + (wm + g) * FPSTR + ks + tq + 4];
            af[3] = smu[FP_OFF + (wm + 8 + g) * FPSTR + ks + tq + 4];
#pragma unroll
            for (int f = 0; f < 16; ++f) {
                uint32_t bf[2];
                bf[0] = smu[FV_OFF + (ks + tq) * FVSTR + f * 8 + g];
                bf[1] = smu[FV_OFF + (ks + tq + 4) * FVSTR + f * 8 + g];
                mma_tf32(o[f], af, bf);
            }
        }
    }

    // ---- epilogue -> g_attn (b, s, h*D+d)
    float i0 = 1.f / l0, i1 = 1.f / l1;
    int b = bh >> 4, h = bh & 15;
    float* base0 = g_attn + ((size_t)(b * SS + r0)) * HID + h * DD;
    float* base1 = g_attn + ((size_t)(b * SS + r1)) * HID + h * DD;
#pragma unroll
    for (int f = 0; f < 16; ++f) {
        int c = f * 8 + 2 * tq;
        *(float2*)(base0 + c) = make_float2(o[f][0] * i0, o[f][1] * i0);
        *(float2*)(base1 + c) = make_float2(o[f][2] * i1, o[f][3] * i1);
    }
}

// ---------------------------------------------------------------------------
extern "C" void kernel_launch(void* const* d_in, const int* in_sizes, int n_in,
                              void* d_out, int out_size) {
    const float* x     = (const float*)d_in[0];
    const float* w_qkv = (const float*)d_in[1];
    const float* w_o   = (const float*)d_in[2];
    float* out = (float*)d_out;

    cudaFuncSetAttribute(mma_gemm<0>, cudaFuncAttributeMaxDynamicSharedMemorySize,
                         GEMM_SMEM);
    cudaFuncSetAttribute(mma_gemm<1>, cudaFuncAttributeMaxDynamicSharedMemorySize,
                         GEMM_SMEM);
    cudaFuncSetAttribute(flash_kernel, cudaFuncAttributeMaxDynamicSharedMemorySize,
                         FL3_SMEM_BYTES);

    // 1. QKV projection (tf32 mma.sync) -> g_q/g_k/g_v (B,H,S,D)
    dim3 g1(N1 / NT, MROWS / MT);
    mma_gemm<0><<<g1, 256, GEMM_SMEM>>>(x, w_qkv, nullptr);

    // 2. RoPE in-place on q,k (tf32-rounded stores)
    rope_kernel<<<(BB * HH * SS * 64) / 256, 256>>>();

    // 3. Flash attention (tf32 mma) -> g_attn (B,S,HID)
    flash_kernel<<<dim3(SS / 128, BB * HH), 256, FL3_SMEM_BYTES>>>();

    // 4. Output projection (tf32 mma.sync) -> d_out
    dim3 g2(N2 / NT, MROWS / MT);
    mma_gemm<1><<<g2, 256, GEMM_SMEM>>>(nullptr, w_o, out);
}

// round 9
// speedup vs baseline: 18.4663x; 1.0648x over previous
#include <cuda_runtime.h>
#include <cstdint>
#include <math.h>

// Problem constants
#define BB   2
#define SS   2048
#define HH   16
#define DD   128
#define HID  2048
#define MROWS 4096          // B*S
#define KDIM  2048
#define N1    6144          // 3*HID
#define N2    2048
#define SCALE 0.08838834764831843f

// Scratch (allocation-free: __device__ globals)
__device__ float g_q[BB*HH*SS*DD];
__device__ float g_k[BB*HH*SS*DD];
__device__ float g_v[BB*HH*SS*DD];
__device__ float g_attn[(size_t)MROWS*HID];
// tf32-pre-rounded copies of GEMM inputs (so GEMM hot loops need no cvt)
__device__ float g_xr[(size_t)MROWS*KDIM];
__device__ float g_wq[(size_t)N1*KDIM];
__device__ float g_wo[(size_t)N2*KDIM];

// ---------------------------------------------------------------------------
// Helpers
// ---------------------------------------------------------------------------
__device__ __forceinline__ void cp_async16(uint32_t dst, const void* src) {
    asm volatile("cp.async.cg.shared.global [%0], [%1], 16;" :: "r"(dst), "l"(src));
}
__device__ __forceinline__ uint32_t smem_u32(const void* p) {
    uint32_t a;
    asm("{ .reg .u64 t; cvta.to.shared.u64 t, %1; cvt.u32.u64 %0, t; }"
        : "=r"(a) : "l"(p));
    return a;
}
__device__ __forceinline__ uint32_t f2tf(float f) {
    uint32_t u;
    asm("cvt.rna.tf32.f32 %0, %1;" : "=r"(u) : "f"(f));
    return u;
}
__device__ __forceinline__ float tfround(float f) { return __uint_as_float(f2tf(f)); }

// D += A*B : m16n8k8 tf32 (row.col)
__device__ __forceinline__ void mma_tf32(float* d, const uint32_t* a, const uint32_t* b) {
    asm volatile(
        "mma.sync.aligned.m16n8k8.row.col.f32.tf32.tf32.f32 "
        "{%0,%1,%2,%3}, {%4,%5,%6,%7}, {%8,%9}, {%0,%1,%2,%3};"
        : "+f"(d[0]), "+f"(d[1]), "+f"(d[2]), "+f"(d[3])
        : "r"(a[0]), "r"(a[1]), "r"(a[2]), "r"(a[3]), "r"(b[0]), "r"(b[1]));
}

// ---------------------------------------------------------------------------
// Pre-round pass: x, w_qkv, w_o -> tf32-rounded copies (float4 grid-stride).
// ---------------------------------------------------------------------------
#define NX  ((size_t)MROWS*KDIM)     // 8388608
#define NWQ ((size_t)N1*KDIM)        // 12582912
#define NWO ((size_t)N2*KDIM)        // 4194304
#define NTOT4 ((NX + NWQ + NWO) / 4) // 6291456 float4s

__global__ __launch_bounds__(256) void preround_kernel(const float* __restrict__ x,
                                                       const float* __restrict__ wq,
                                                       const float* __restrict__ wo) {
    size_t i4 = (size_t)blockIdx.x * 256 + threadIdx.x;
    if (i4 >= NTOT4) return;
    size_t i = i4 * 4;
    const float* src;
    float* dst;
    if (i < NX)                { src = x  + i;              dst = g_xr + i; }
    else if (i < NX + NWQ)     { src = wq + (i - NX);       dst = g_wq + (i - NX); }
    else                       { src = wo + (i - NX - NWQ); dst = g_wo + (i - NX - NWQ); }
    float4 v = *(const float4*)src;
    v.x = tfround(v.x); v.y = tfround(v.y);
    v.z = tfround(v.z); v.w = tfround(v.w);
    *(float4*)dst = v;
}

// ---------------------------------------------------------------------------
// tf32 mma.sync GEMM — inputs pre-rounded, NO cvt in mainloop.
// CTA tile 128x128, K-chunk 32, 256 threads (8 warps: 4 m x 2 n).
// MODE 0: A = g_xr, B = g_wq, scatter qkv -> g_q/g_k/g_v (B,H,S,D)
// MODE 1: A = g_attn (rounded at flash epilogue), B = g_wo, C = d_out
// ---------------------------------------------------------------------------
#define MT 128
#define NT 128
#define KC 32
#define ASTR 36
#define STG_FLOATS (MT*ASTR + NT*ASTR)
#define GEMM_SMEM  (2 * STG_FLOATS * 4)
#define NCHUNK (KDIM / KC)

template<int MODE>
__global__ __launch_bounds__(256) void mma_gemm(float* __restrict__ C) {
    extern __shared__ float sm[];
    uint32_t sb = smem_u32(sm);
    int tid = threadIdx.x;
    int wid = tid >> 5;
    int lid = tid & 31;
    int g   = lid >> 2;
    int tq  = lid & 3;

    const float* A = (MODE == 0) ? g_xr : g_attn;
    const float* W = (MODE == 0) ? g_wq : g_wo;
    int m0 = blockIdx.y * MT;
    int n0 = blockIdx.x * NT;

    int wm = (wid & 3) * 32;
    int wn = (wid >> 2) * 64;

    float acc[2][8][4];
#pragma unroll
    for (int i = 0; i < 2; ++i)
#pragma unroll
        for (int j = 0; j < 8; ++j)
#pragma unroll
            for (int q = 0; q < 4; ++q) acc[i][j][q] = 0.f;

    auto load_stage = [&](int stg, int k0) {
        uint32_t abase = sb + stg * STG_FLOATS * 4;
        uint32_t bbase = abase + MT * ASTR * 4;
#pragma unroll
        for (int j = 0; j < 4; ++j) {
            int ci = tid + j * 256;
            int r = ci >> 3, kc = ci & 7;
            cp_async16(abase + (r * ASTR + kc * 4) * 4,
                       A + (size_t)(m0 + r) * KDIM + k0 + kc * 4);
        }
#pragma unroll
        for (int j = 0; j < 4; ++j) {
            int ci = tid + j * 256;
            int r = ci >> 3, kc = ci & 7;
            cp_async16(bbase + (r * ASTR + kc * 4) * 4,
                       W + (size_t)(n0 + r) * KDIM + k0 + kc * 4);
        }
    };

    load_stage(0, 0);
    asm volatile("cp.async.commit_group;" ::: "memory");

    for (int u = 0; u < NCHUNK; ++u) {
        if (u + 1 < NCHUNK) {
            load_stage((u + 1) & 1, (u + 1) * KC);
            asm volatile("cp.async.commit_group;" ::: "memory");
            asm volatile("cp.async.wait_group 1;" ::: "memory");
        } else {
            asm volatile("cp.async.wait_group 0;" ::: "memory");
        }
        __syncthreads();

        const uint32_t* As = (const uint32_t*)(sm + (u & 1) * STG_FLOATS);
        const uint32_t* Bs = As + MT * ASTR;

#pragma unroll
        for (int ks = 0; ks < KC; ks += 8) {
            uint32_t af[2][4], bf[8][2];
#pragma unroll
            for (int im = 0; im < 2; ++im) {
                int row = wm + im * 16 + g;
                af[im][0] = As[row * ASTR + ks + tq];
                af[im][1] = As[(row + 8) * ASTR + ks + tq];
                af[im][2] = As[row * ASTR + ks + tq + 4];
                af[im][3] = As[(row + 8) * ASTR + ks + tq + 4];
            }
#pragma unroll
            for (int in_ = 0; in_ < 8; ++in_) {
                int col = wn + in_ * 8 + g;
                bf[in_][0] = Bs[col * ASTR + ks + tq];
                bf[in_][1] = Bs[col * ASTR + ks + tq + 4];
            }
#pragma unroll
            for (int im = 0; im < 2; ++im)
#pragma unroll
                for (int in_ = 0; in_ < 8; ++in_)
                    mma_tf32(acc[im][in_], af[im], bf[in_]);
        }
        __syncthreads();
    }

#pragma unroll
    for (int im = 0; im < 2; ++im) {
#pragma unroll
        for (int half = 0; half < 2; ++half) {
            int m = m0 + wm + im * 16 + g + half * 8;
            float* dstrow;
            bool rnd = false;
            if (MODE == 0) {
                int qkvi = n0 >> 11;
                int rem  = n0 & 2047;
                int h = rem >> 7;
                int b = m >> 11, s = m & 2047;
                float* dst = (qkvi == 0) ? g_q : ((qkvi == 1) ? g_k : g_v);
                rnd = (qkvi == 2);     // pre-round V for flash mma
                dstrow = dst + (((size_t)(b * HH + h)) * SS + s) * DD;
            } else {
                dstrow = C + (size_t)m * N2 + n0;
            }
#pragma unroll
            for (int in_ = 0; in_ < 8; ++in_) {
                int dcol = wn + in_ * 8 + tq * 2;
                float2 v;
                v.x = acc[im][in_][half * 2 + 0];
                v.y = acc[im][in_][half * 2 + 1];
                if (rnd) { v.x = tfround(v.x); v.y = tfround(v.y); }
                *(float2*)(dstrow + dcol) = v;
            }
        }
    }
}

// ---------------------------------------------------------------------------
// RoPE in-place on g_q, g_k; stores tf32-rounded.
// ---------------------------------------------------------------------------
__global__ __launch_bounds__(256) void rope_kernel() {
    int idx = blockIdx.x * 256 + threadIdx.x;
    int d   = idx & 63;
    int row = idx >> 6;
    int s   = row & (SS - 1);

    float inv = expf(-(float)d * 0.14391156831212787f);
    float ang = (float)s * inv;
    float c, sn;
    sincosf(ang, &sn, &c);

    size_t base = (size_t)row * DD;
    float q0 = g_q[base + d], q1 = g_q[base + d + 64];
    g_q[base + d]      = tfround(q0 * c - q1 * sn);
    g_q[base + d + 64] = tfround(q1 * c + q0 * sn);
    float k0 = g_k[base + d], k1 = g_k[base + d + 64];
    g_k[base + d]      = tfround(k0 * c - k1 * sn);
    g_k[base + d + 64] = tfround(k1 * c + k0 * sn);
}

// ---------------------------------------------------------------------------
// Flash attention v3 — tf32 mma.sync for QK^T and PV (R7, epilogue rounded).
// ---------------------------------------------------------------------------
#define FQSTR 132
#define FKSTR 132
#define FVSTR 136
#define FPSTR 68
#define FQ_OFF 0
#define FK_OFF (128*FQSTR)
#define FK_BUF (64*FKSTR)
#define FV_OFF (FK_OFF + 2*FK_BUF)
#define FP_OFF (FV_OFF + 64*FVSTR)
#define FL3_FLOATS (FP_OFF + 128*FPSTR)
#define FL3_SMEM_BYTES (FL3_FLOATS * 4)

__global__ __launch_bounds__(256) void flash_kernel() {
    extern __shared__ float sm[];
    uint32_t sb = smem_u32(sm);
    const uint32_t* smu = (const uint32_t*)sm;

    int tid = threadIdx.x;
    int wid = tid >> 5;
    int lid = tid & 31;
    int g   = lid >> 2;
    int tq  = lid & 3;
    int wm  = wid * 16;

    int bh = blockIdx.y;
    int qt = 15 - (int)blockIdx.x;
    int q0 = qt * 128;
    int ntiles = 2 * qt + 2;

    const float* Qg = g_q + (size_t)bh * (SS * DD);
    const float* Kg = g_k + (size_t)bh * (SS * DD);
    const float* Vg = g_v + (size_t)bh * (SS * DD);

#pragma unroll
    for (int j = 0; j < 16; ++j) {
        int ci = tid + j * 256;
        int r = ci >> 5, kc = ci & 31;
        cp_async16(sb + (FQ_OFF + r * FQSTR + kc * 4) * 4,
                   Qg + (size_t)(q0 + r) * DD + kc * 4);
    }
#pragma unroll
    for (int j = 0; j < 8; ++j) {
        int ci = tid + j * 256;
        int r = ci >> 5, kc = ci & 31;
        cp_async16(sb + (FK_OFF + r * FKSTR + kc * 4) * 4,
                   Kg + (size_t)r * DD + kc * 4);
    }
    asm volatile("cp.async.commit_group;" ::: "memory");

    int r0 = q0 + wm + g;
    int r1 = r0 + 8;

    float mx0 = -1e30f, mx1 = -1e30f, l0 = 0.f, l1 = 0.f;
    float o[16][4];
#pragma unroll
    for (int f = 0; f < 16; ++f)
#pragma unroll
        for (int q = 0; q < 4; ++q) o[f][q] = 0.f;

    for (int jt = 0; jt < ntiles; ++jt) {
        int kbase = jt * 64;
        bool haveNext = (jt + 1 < ntiles);
        if (jt > 0) __syncthreads();

#pragma unroll
        for (int j = 0; j < 8; ++j) {
            int ci = tid + j * 256;
            int r = ci >> 5, kc = ci & 31;
            cp_async16(sb + (FV_OFF + r * FVSTR + kc * 4) * 4,
                       Vg + (size_t)(kbase + r) * DD + kc * 4);
        }
        asm volatile("cp.async.commit_group;" ::: "memory");
        if (haveNext) {
            int nb = (jt + 1) & 1;
#pragma unroll
            for (int j = 0; j < 8; ++j) {
                int ci = tid + j * 256;
                int r = ci >> 5, kc = ci & 31;
                cp_async16(sb + (FK_OFF + nb * FK_BUF + r * FKSTR + kc * 4) * 4,
                           Kg + (size_t)(kbase + 64 + r) * DD + kc * 4);
            }
            asm volatile("cp.async.commit_group;" ::: "memory");
            asm volatile("cp.async.wait_group 2;" ::: "memory");
        } else {
            asm volatile("cp.async.wait_group 1;" ::: "memory");
        }
        __syncthreads();

        const uint32_t* Ku = smu + FK_OFF + (jt & 1) * FK_BUF;
        float s[8][4];
#pragma unroll
        for (int f = 0; f < 8; ++f)
#pragma unroll
            for (int q = 0; q < 4; ++q) s[f][q] = 0.f;

#pragma unroll
        for (int ks = 0; ks < 128; ks += 8) {
            uint32_t af[4];
            af[0] = smu[FQ_OFF + (wm + g) * FQSTR + ks + tq];
            af[1] = smu[FQ_OFF + (wm + 8 + g) * FQSTR + ks + tq];
            af[2] = smu[FQ_OFF + (wm + g) * FQSTR + ks + tq + 4];
            af[3] = smu[FQ_OFF + (wm + 8 + g) * FQSTR + ks + tq + 4];
#pragma unroll
            for (int f = 0; f < 8; ++f) {
                uint32_t bf[2];
                bf[0] = Ku[(f * 8 + g) * FKSTR + ks + tq];
                bf[1] = Ku[(f * 8 + g) * FKSTR + ks + tq + 4];
                mma_tf32(s[f], af, bf);
            }
        }

        if (haveNext) asm volatile("cp.async.wait_group 1;" ::: "memory");
        else          asm volatile("cp.async.wait_group 0;" ::: "memory");
        __syncthreads();

        bool diag = (jt >= 2 * qt);
        float tm0 = -1e30f, tm1 = -1e30f;
#pragma unroll
        for (int f = 0; f < 8; ++f) {
            float v0 = s[f][0] * SCALE, v1 = s[f][1] * SCALE;
            float v2 = s[f][2] * SCALE, v3 = s[f][3] * SCALE;
            if (diag) {
                int c0 = kbase + f * 8 + 2 * tq, c1 = c0 + 1;
                if (c0 > r0) v0 = -1e30f;
                if (c1 > r0) v1 = -1e30f;
                if (c0 > r1) v2 = -1e30f;
                if (c1 > r1) v3 = -1e30f;
            }
            s[f][0] = v0; s[f][1] = v1; s[f][2] = v2; s[f][3] = v3;
            tm0 = fmaxf(tm0, fmaxf(v0, v1));
            tm1 = fmaxf(tm1, fmaxf(v2, v3));
        }
        tm0 = fmaxf(tm0, __shfl_xor_sync(0xffffffffu, tm0, 1));
        tm0 = fmaxf(tm0, __shfl_xor_sync(0xffffffffu, tm0, 2));
        tm1 = fmaxf(tm1, __shfl_xor_sync(0xffffffffu, tm1, 1));
        tm1 = fmaxf(tm1, __shfl_xor_sync(0xffffffffu, tm1, 2));
        float mn0 = fmaxf(mx0, tm0), mn1 = fmaxf(mx1, tm1);

        float ps0 = 0.f, ps1 = 0.f;
#pragma unroll
        for (int f = 0; f < 8; ++f) {
            float p0 = tfround(__expf(s[f][0] - mn0));
            float p1 = tfround(__expf(s[f][1] - mn0));
            float p2 = tfround(__expf(s[f][2] - mn1));
            float p3 = tfround(__expf(s[f][3] - mn1));
            ps0 += p0 + p1;
            ps1 += p2 + p3;
            int c = f * 8 + 2 * tq;
            *(float2*)&sm[FP_OFF + (wm + g) * FPSTR + c]     = make_float2(p0, p1);
            *(float2*)&sm[FP_OFF + (wm + 8 + g) * FPSTR + c] = make_float2(p2, p3);
        }
        ps0 += __shfl_xor_sync(0xffffffffu, ps0, 1);
        ps0 += __shfl_xor_sync(0xffffffffu, ps0, 2);
        ps1 += __shfl_xor_sync(0xffffffffu, ps1, 1);
        ps1 += __shfl_xor_sync(0xffffffffu, ps1, 2);

        float a0 = __expf(mx0 - mn0), a1 = __expf(mx1 - mn1);
        l0 = l0 * a0 + ps0;
        l1 = l1 * a1 + ps1;
        mx0 = mn0; mx1 = mn1;
#pragma unroll
        for (int f = 0; f < 16; ++f) {
            o[f][0] *= a0; o[f][1] *= a0;
            o[f][2] *= a1; o[f][3] *= a1;
        }
        __syncthreads();

#pragma unroll
        for (int ks = 0; ks < 64; ks += 8) {
            uint32_t af[4];
            af[0] = smu[FP_OFF + (wm + g) * FPSTR + ks + tq];
            af[1] = smu[FP_OFF + (wm + 8 + g) * FPSTR + ks + tq];
            af[2] = smu[FP_OFF + (wm + g) * FPSTR + ks + tq + 4];
            af[3] = smu[FP_OFF + (wm + 8 + g) * FPSTR + ks + tq + 4];
#pragma unroll
            for (int f = 0; f < 16; ++f) {
                uint32_t bf[2];
                bf[0] = smu[FV_OFF + (ks + tq) * FVSTR + f * 8 + g];
                bf[1] = smu[FV_OFF + (ks + tq + 4) * FVSTR + f * 8 + g];
                mma_tf32(o[f], af, bf);
            }
        }
    }

    // epilogue -> g_attn, tf32-rounded so GEMM2 needs no cvt
    float i0 = 1.f / l0, i1 = 1.f / l1;
    int b = bh >> 4, h = bh & 15;
    float* base0 = g_attn + ((size_t)(b * SS + r0)) * HID + h * DD;
    float* base1 = g_attn + ((size_t)(b * SS + r1)) * HID + h * DD;
#pragma unroll
    for (int f = 0; f < 16; ++f) {
        int c = f * 8 + 2 * tq;
        *(float2*)(base0 + c) = make_float2(tfround(o[f][0] * i0), tfround(o[f][1] * i0));
        *(float2*)(base1 + c) = make_float2(tfround(o[f][2] * i1), tfround(o[f][3] * i1));
    }
}

// ---------------------------------------------------------------------------
extern "C" void kernel_launch(void* const* d_in, const int* in_sizes, int n_in,
                              void* d_out, int out_size) {
    const float* x     = (const float*)d_in[0];
    const float* w_qkv = (const float*)d_in[1];
    const float* w_o   = (const float*)d_in[2];
    float* out = (float*)d_out;

    cudaFuncSetAttribute(mma_gemm<0>, cudaFuncAttributeMaxDynamicSharedMemorySize,
                         GEMM_SMEM);
    cudaFuncSetAttribute(mma_gemm<1>, cudaFuncAttributeMaxDynamicSharedMemorySize,
                         GEMM_SMEM);
    cudaFuncSetAttribute(flash_kernel, cudaFuncAttributeMaxDynamicSharedMemorySize,
                         FL3_SMEM_BYTES);

    // 0. Pre-round GEMM inputs to tf32
    preround_kernel<<<(unsigned)((NTOT4 + 255) / 256), 256>>>(x, w_qkv, w_o);

    // 1. QKV projection -> g_q/g_k/g_v (B,H,S,D)
    dim3 g1(N1 / NT, MROWS / MT);
    mma_gemm<0><<<g1, 256, GEMM_SMEM>>>(nullptr);

    // 2. RoPE in-place on q,k (tf32-rounded stores)
    rope_kernel<<<(BB * HH * SS * 64) / 256, 256>>>();

    // 3. Flash attention (tf32 mma) -> g_attn (B,S,HID)
    flash_kernel<<<dim3(SS / 128, BB * HH), 256, FL3_SMEM_BYTES>>>();

    // 4. Output projection -> d_out
    dim3 g2(N2 / NT, MROWS / MT);
    mma_gemm<1><<<g2, 256, GEMM_SMEM>>>(out);
}

// round 10
// speedup vs baseline: 33.9431x; 1.8381x over previous
#include <cuda_runtime.h>
#include <cuda_fp16.h>
#include <cstdint>
#include <math.h>

// Problem constants
#define BB   2
#define SS   2048
#define HH   16
#define DD   128
#define HID  2048
#define MROWS 4096          // B*S
#define KDIM  2048
#define N1    6144          // 3*HID
#define N2    2048
#define SCALE 0.08838834764831843f

// Scratch (allocation-free: __device__ globals) — all fp16 now
__device__ __half g_q[BB*HH*SS*DD];            // (b,h,s,d)
__device__ __half g_k[BB*HH*SS*DD];            // (b,h,s,d)
__device__ __half g_v[BB*HH*SS*DD];            // (b,h,d,s)  TRANSPOSED
__device__ __half g_attn[(size_t)MROWS*HID];   // (b,s,hid)
__device__ __half g_xr[(size_t)MROWS*KDIM];
__device__ __half g_wq[(size_t)N1*KDIM];
__device__ __half g_wo[(size_t)N2*KDIM];

// ---------------------------------------------------------------------------
// Helpers
// ---------------------------------------------------------------------------
__device__ __forceinline__ void cp_async16(uint32_t dst, const void* src) {
    asm volatile("cp.async.cg.shared.global [%0], [%1], 16;" :: "r"(dst), "l"(src));
}
__device__ __forceinline__ uint32_t smem_u32(const void* p) {
    uint32_t a;
    asm("{ .reg .u64 t; cvta.to.shared.u64 t, %1; cvt.u32.u64 %0, t; }"
        : "=r"(a) : "l"(p));
    return a;
}
// D += A*B : m16n8k16 f16 (row.col), fp32 accumulate
__device__ __forceinline__ void mma_f16(float* d, const uint32_t* a, const uint32_t* b) {
    asm volatile(
        "mma.sync.aligned.m16n8k16.row.col.f32.f16.f16.f32 "
        "{%0,%1,%2,%3}, {%4,%5,%6,%7}, {%8,%9}, {%0,%1,%2,%3};"
        : "+f"(d[0]), "+f"(d[1]), "+f"(d[2]), "+f"(d[3])
        : "r"(a[0]), "r"(a[1]), "r"(a[2]), "r"(a[3]), "r"(b[0]), "r"(b[1]));
}

// ---------------------------------------------------------------------------
// Pre-round pass: x, w_qkv, w_o (fp32) -> fp16 copies.
// ---------------------------------------------------------------------------
#define NX  ((size_t)MROWS*KDIM)
#define NWQ ((size_t)N1*KDIM)
#define NWO ((size_t)N2*KDIM)
#define NTOT4 ((NX + NWQ + NWO) / 4)

__global__ __launch_bounds__(256) void preround_kernel(const float* __restrict__ x,
                                                       const float* __restrict__ wq,
                                                       const float* __restrict__ wo) {
    size_t i4 = (size_t)blockIdx.x * 256 + threadIdx.x;
    if (i4 >= NTOT4) return;
    size_t i = i4 * 4;
    const float* src;
    __half* dst;
    if (i < NX)            { src = x  + i;              dst = g_xr + i; }
    else if (i < NX + NWQ) { src = wq + (i - NX);       dst = g_wq + (i - NX); }
    else                   { src = wo + (i - NX - NWQ); dst = g_wo + (i - NX - NWQ); }
    float4 v = *(const float4*)src;
    __half2 h0 = __floats2half2_rn(v.x, v.y);
    __half2 h1 = __floats2half2_rn(v.z, v.w);
    uint2 u;
    u.x = *(uint32_t*)&h0;
    u.y = *(uint32_t*)&h1;
    *(uint2*)dst = u;
}

// ---------------------------------------------------------------------------
// fp16 mma.sync GEMM: C[m,n] = sum_k A[m,k] * W[n,k]
// CTA tile 128x128, K-chunk 64 halves, 256 threads (8 warps: 4m x 2n),
// warp tile 32x64, m16n8k16, 2-stage cp.async pipeline.
// smem rows stride 72 halves (STRH/2 = 36 ≡ 4 mod 32 -> conflict-free).
// MODE 0: A=g_xr, W=g_wq, scatter q/k (b,h,s,d) + v transposed (b,h,d,s)
// MODE 1: A=g_attn, W=g_wo, C=d_out (fp32)
// ---------------------------------------------------------------------------
#define MT 128
#define NT 128
#define KCH 64
#define STRH 72
#define STG_HALVES (MT*STRH + NT*STRH)        // 18432 halves
#define GEMM_SMEM  (2 * STG_HALVES * 2)       // 73728 bytes
#define GNCHUNK (KDIM / KCH)                  // 32

template<int MODE>
__global__ __launch_bounds__(256) void mma_gemm(float* __restrict__ C) {
    extern __shared__ __half smh[];
    uint32_t sb = smem_u32(smh);
    const uint32_t* smu = (const uint32_t*)smh;
    int tid = threadIdx.x;
    int wid = tid >> 5;
    int lid = tid & 31;
    int g   = lid >> 2;
    int tq  = lid & 3;

    const __half* A = (MODE == 0) ? g_xr : g_attn;
    const __half* W = (MODE == 0) ? g_wq : g_wo;
    int m0 = blockIdx.y * MT;
    int n0 = blockIdx.x * NT;

    int wm = (wid & 3) * 32;
    int wn = (wid >> 2) * 64;

    float acc[2][8][4];
#pragma unroll
    for (int i = 0; i < 2; ++i)
#pragma unroll
        for (int j = 0; j < 8; ++j)
#pragma unroll
            for (int q = 0; q < 4; ++q) acc[i][j][q] = 0.f;

    auto load_stage = [&](int stg, int k0) {
        uint32_t abase = sb + stg * STG_HALVES * 2;
        uint32_t bbase = abase + MT * STRH * 2;
#pragma unroll
        for (int j = 0; j < 4; ++j) {            // A: 1024 16B chunks
            int ci = tid + j * 256;
            int r = ci >> 3, kc = ci & 7;
            cp_async16(abase + (r * STRH + kc * 8) * 2,
                       A + (size_t)(m0 + r) * KDIM + k0 + kc * 8);
        }
#pragma unroll
        for (int j = 0; j < 4; ++j) {            // B: 1024 16B chunks
            int ci = tid + j * 256;
            int r = ci >> 3, kc = ci & 7;
            cp_async16(bbase + (r * STRH + kc * 8) * 2,
                       W + (size_t)(n0 + r) * KDIM + k0 + kc * 8);
        }
    };

    load_stage(0, 0);
    asm volatile("cp.async.commit_group;" ::: "memory");

    for (int u = 0; u < GNCHUNK; ++u) {
        if (u + 1 < GNCHUNK) {
            load_stage((u + 1) & 1, (u + 1) * KCH);
            asm volatile("cp.async.commit_group;" ::: "memory");
            asm volatile("cp.async.wait_group 1;" ::: "memory");
        } else {
            asm volatile("cp.async.wait_group 0;" ::: "memory");
        }
        __syncthreads();

        const uint32_t* As = smu + (u & 1) * (STG_HALVES / 2);
        const uint32_t* Bs = As + (MT * STRH) / 2;

#pragma unroll
        for (int ks = 0; ks < 4; ++ks) {          // 4 k-steps of 16 halves
            int ku = ks * 8;                      // u32 offset
            uint32_t af[2][4], bf[8][2];
#pragma unroll
            for (int im = 0; im < 2; ++im) {
                int r36a = (wm + im * 16 + g) * 36;
                int r36b = (wm + im * 16 + 8 + g) * 36;
                af[im][0] = As[r36a + ku + tq];
                af[im][1] = As[r36b + ku + tq];
                af[im][2] = As[r36a + ku + tq + 4];
                af[im][3] = As[r36b + ku + tq + 4];
            }
#pragma unroll
            for (int in_ = 0; in_ < 8; ++in_) {
                int c36 = (wn + in_ * 8 + g) * 36;
                bf[in_][0] = Bs[c36 + ku + tq];
                bf[in_][1] = Bs[c36 + ku + tq + 4];
            }
#pragma unroll
            for (int im = 0; im < 2; ++im)
#pragma unroll
                for (int in_ = 0; in_ < 8; ++in_)
                    mma_f16(acc[im][in_], af[im], bf[in_]);
        }
        __syncthreads();
    }

#pragma unroll
    for (int im = 0; im < 2; ++im) {
#pragma unroll
        for (int half = 0; half < 2; ++half) {
            int m = m0 + wm + im * 16 + g + half * 8;
            if (MODE == 0) {
                int qkvi = n0 >> 11;
                int rem  = n0 & 2047;
                int h = rem >> 7;
                int b = m >> 11, s = m & 2047;
                if (qkvi < 2) {
                    __half* dst = (qkvi == 0) ? g_q : g_k;
                    __half* row = dst + (((size_t)(b * HH + h)) * SS + s) * DD;
#pragma unroll
                    for (int in_ = 0; in_ < 8; ++in_) {
                        int dcol = wn + in_ * 8 + tq * 2;
                        __half2 hv = __floats2half2_rn(acc[im][in_][half * 2 + 0],
                                                       acc[im][in_][half * 2 + 1]);
                        *(__half2*)(row + dcol) = hv;
                    }
                } else {
                    // V transposed: (b,h,d,s)
                    __half* vb = g_v + ((size_t)(b * HH + h)) * DD * SS + s;
#pragma unroll
                    for (int in_ = 0; in_ < 8; ++in_) {
                        int dcol = wn + in_ * 8 + tq * 2;
                        vb[(size_t)dcol * SS]       = __float2half_rn(acc[im][in_][half * 2 + 0]);
                        vb[(size_t)(dcol + 1) * SS] = __float2half_rn(acc[im][in_][half * 2 + 1]);
                    }
                }
            } else {
                float* row = C + (size_t)m * N2 + n0;
#pragma unroll
                for (int in_ = 0; in_ < 8; ++in_) {
                    int dcol = wn + in_ * 8 + tq * 2;
                    float2 v;
                    v.x = acc[im][in_][half * 2 + 0];
                    v.y = acc[im][in_][half * 2 + 1];
                    *(float2*)(row + dcol) = v;
                }
            }
        }
    }
}

// ---------------------------------------------------------------------------
// RoPE in-place on g_q, g_k (fp16 storage, fp32 math).
// ---------------------------------------------------------------------------
__global__ __launch_bounds__(256) void rope_kernel() {
    int idx = blockIdx.x * 256 + threadIdx.x;
    int d   = idx & 63;
    int row = idx >> 6;
    int s   = row & (SS - 1);

    float inv = expf(-(float)d * 0.14391156831212787f);
    float ang = (float)s * inv;
    float c, sn;
    sincosf(ang, &sn, &c);

    size_t base = (size_t)row * DD;
    float q0 = __half2float(g_q[base + d]), q1 = __half2float(g_q[base + d + 64]);
    g_q[base + d]      = __float2half_rn(q0 * c - q1 * sn);
    g_q[base + d + 64] = __float2half_rn(q1 * c + q0 * sn);
    float k0 = __half2float(g_k[base + d]), k1 = __half2float(g_k[base + d + 64]);
    g_k[base + d]      = __float2half_rn(k0 * c - k1 * sn);
    g_k[base + d + 64] = __float2half_rn(k1 * c + k0 * sn);
}

// ---------------------------------------------------------------------------
// Flash attention v4 — fp16 m16n8k16 for QK^T and PV.
// q-tile 128 (8 warps x 16 rows), k-tile 64. V is K-major (d rows, s cols).
// smem halves: Q[128][136] | K 2x[64][136] | V[128][72] | P[128][72]
// 106496 bytes -> 2 CTAs/SM.
// ---------------------------------------------------------------------------
#define QSTRH 136
#define VSTRH 72
#define PSTRH 72
#define FQ_H 0
#define FK_H (128*QSTRH)                 // 17408
#define FK_BUFH (64*QSTRH)               // 8704
#define FV_H (FK_H + 2*FK_BUFH)          // 34816
#define FP_H (FV_H + 128*VSTRH)          // 44032
#define FL_H (FP_H + 128*PSTRH)          // 53248 halves
#define FL4_SMEM_BYTES (FL_H * 2)        // 106496

__global__ __launch_bounds__(256) void flash_kernel() {
    extern __shared__ __half smh[];
    uint32_t sb = smem_u32(smh);
    const uint32_t* smu = (const uint32_t*)smh;

    int tid = threadIdx.x;
    int wid = tid >> 5;
    int lid = tid & 31;
    int g   = lid >> 2;
    int tq  = lid & 3;
    int wm  = wid * 16;

    int bh = blockIdx.y;
    int qt = 15 - (int)blockIdx.x;
    int q0 = qt * 128;
    int ntiles = 2 * qt + 2;

    const __half* Qg = g_q + (size_t)bh * (SS * DD);
    const __half* Kg = g_k + (size_t)bh * (SS * DD);
    const __half* Vg = g_v + (size_t)bh * (DD * SS);   // (d, s)

    // prologue: Q (128 x 128 halves) + K tile 0
#pragma unroll
    for (int j = 0; j < 8; ++j) {
        int ci = tid + j * 256;            // 2048 chunks
        int r = ci >> 4, kc = ci & 15;
        cp_async16(sb + (FQ_H + r * QSTRH + kc * 8) * 2,
                   Qg + (size_t)(q0 + r) * DD + kc * 8);
    }
#pragma unroll
    for (int j = 0; j < 4; ++j) {
        int ci = tid + j * 256;            // 1024 chunks
        int r = ci >> 4, kc = ci & 15;
        cp_async16(sb + (FK_H + r * QSTRH + kc * 8) * 2,
                   Kg + (size_t)r * DD + kc * 8);
    }
    asm volatile("cp.async.commit_group;" ::: "memory");

    int r0 = q0 + wm + g;
    int r1 = r0 + 8;

    float mx0 = -1e30f, mx1 = -1e30f, l0 = 0.f, l1 = 0.f;
    float o[16][4];
#pragma unroll
    for (int f = 0; f < 16; ++f)
#pragma unroll
        for (int q = 0; q < 4; ++q) o[f][q] = 0.f;

    for (int jt = 0; jt < ntiles; ++jt) {
        int kbase = jt * 64;
        bool haveNext = (jt + 1 < ntiles);
        if (jt > 0) __syncthreads();

        // prefetch V[jt] (128 d-rows x 64 s-halves) and K[jt+1]
#pragma unroll
        for (int j = 0; j < 4; ++j) {
            int ci = tid + j * 256;        // 1024 chunks
            int r = ci >> 3, kc = ci & 7;
            cp_async16(sb + (FV_H + r * VSTRH + kc * 8) * 2,
                       Vg + (size_t)r * SS + kbase + kc * 8);
        }
        asm volatile("cp.async.commit_group;" ::: "memory");
        if (haveNext) {
            int nb = (jt + 1) & 1;
#pragma unroll
            for (int j = 0; j < 4; ++j) {
                int ci = tid + j * 256;
                int r = ci >> 4, kc = ci & 15;
                cp_async16(sb + (FK_H + nb * FK_BUFH + r * QSTRH + kc * 8) * 2,
                           Kg + (size_t)(kbase + 64 + r) * DD + kc * 8);
            }
            asm volatile("cp.async.commit_group;" ::: "memory");
            asm volatile("cp.async.wait_group 2;" ::: "memory");
        } else {
            asm volatile("cp.async.wait_group 1;" ::: "memory");
        }
        __syncthreads();

        // ---- S = Q K^T : 8 k-steps of 16, 8 n-frags
        const uint32_t* Ku = smu + (FK_H >> 1) + ((jt & 1) ? (FK_BUFH >> 1) : 0);
        const uint32_t* Qu = smu + (FQ_H >> 1);
        float s[8][4];
#pragma unroll
        for (int f = 0; f < 8; ++f)
#pragma unroll
            for (int q = 0; q < 4; ++q) s[f][q] = 0.f;

#pragma unroll
        for (int ks = 0; ks < 8; ++ks) {
            int ku = ks * 8;
            uint32_t af[4];
            int ra = (wm + g) * 68, rb = (wm + 8 + g) * 68;
            af[0] = Qu[ra + ku + tq];
            af[1] = Qu[rb + ku + tq];
            af[2] = Qu[ra + ku + tq + 4];
            af[3] = Qu[rb + ku + tq + 4];
#pragma unroll
            for (int f = 0; f < 8; ++f) {
                int c68 = (f * 8 + g) * 68;
                uint32_t bf[2];
                bf[0] = Ku[c68 + ku + tq];
                bf[1] = Ku[c68 + ku + tq + 4];
                mma_f16(s[f], af, bf);
            }
        }

        if (haveNext) asm volatile("cp.async.wait_group 1;" ::: "memory");
        else          asm volatile("cp.async.wait_group 0;" ::: "memory");
        __syncthreads();

        // ---- online softmax
        bool diag = (jt >= 2 * qt);
        float tm0 = -1e30f, tm1 = -1e30f;
#pragma unroll
        for (int f = 0; f < 8; ++f) {
            float v0 = s[f][0] * SCALE, v1 = s[f][1] * SCALE;
            float v2 = s[f][2] * SCALE, v3 = s[f][3] * SCALE;
            if (diag) {
                int c0 = kbase + f * 8 + 2 * tq, c1 = c0 + 1;
                if (c0 > r0) v0 = -1e30f;
                if (c1 > r0) v1 = -1e30f;
                if (c0 > r1) v2 = -1e30f;
                if (c1 > r1) v3 = -1e30f;
            }
            s[f][0] = v0; s[f][1] = v1; s[f][2] = v2; s[f][3] = v3;
            tm0 = fmaxf(tm0, fmaxf(v0, v1));
            tm1 = fmaxf(tm1, fmaxf(v2, v3));
        }
        tm0 = fmaxf(tm0, __shfl_xor_sync(0xffffffffu, tm0, 1));
        tm0 = fmaxf(tm0, __shfl_xor_sync(0xffffffffu, tm0, 2));
        tm1 = fmaxf(tm1, __shfl_xor_sync(0xffffffffu, tm1, 1));
        tm1 = fmaxf(tm1, __shfl_xor_sync(0xffffffffu, tm1, 2));
        float mn0 = fmaxf(mx0, tm0), mn1 = fmaxf(mx1, tm1);

        __half2* Ph = (__half2*)smh;
        float ps0 = 0.f, ps1 = 0.f;
#pragma unroll
        for (int f = 0; f < 8; ++f) {
            float p0 = __expf(s[f][0] - mn0);
            float p1 = __expf(s[f][1] - mn0);
            float p2 = __expf(s[f][2] - mn1);
            float p3 = __expf(s[f][3] - mn1);
            __half2 h01 = __floats2half2_rn(p0, p1);
            __half2 h23 = __floats2half2_rn(p2, p3);
            // accumulate l from the rounded values for consistency
            float2 f01 = __half22float2(h01);
            float2 f23 = __half22float2(h23);
            ps0 += f01.x + f01.y;
            ps1 += f23.x + f23.y;
            int i0 = (FP_H >> 1) + (wm + g) * 36 + f * 4 + tq;
            int i1 = (FP_H >> 1) + (wm + 8 + g) * 36 + f * 4 + tq;
            Ph[i0] = h01;
            Ph[i1] = h23;
        }
        ps0 += __shfl_xor_sync(0xffffffffu, ps0, 1);
        ps0 += __shfl_xor_sync(0xffffffffu, ps0, 2);
        ps1 += __shfl_xor_sync(0xffffffffu, ps1, 1);
        ps1 += __shfl_xor_sync(0xffffffffu, ps1, 2);

        float a0 = __expf(mx0 - mn0), a1 = __expf(mx1 - mn1);
        l0 = l0 * a0 + ps0;
        l1 = l1 * a1 + ps1;
        mx0 = mn0; mx1 = mn1;
#pragma unroll
        for (int f = 0; f < 16; ++f) {
            o[f][0] *= a0; o[f][1] *= a0;
            o[f][2] *= a1; o[f][3] *= a1;
        }
        __syncthreads();

        // ---- O += P V : 4 k-steps of 16, 16 n-frags (V is K-major [d][s])
        const uint32_t* Pu = smu + (FP_H >> 1);
        const uint32_t* Vu = smu + (FV_H >> 1);
#pragma unroll
        for (int ks = 0; ks < 4; ++ks) {
            int ku = ks * 8;
            uint32_t af[4];
            int ra = (wm + g) * 36, rb = (wm + 8 + g) * 36;
            af[0] = Pu[ra + ku + tq];
            af[1] = Pu[rb + ku + tq];
            af[2] = Pu[ra + ku + tq + 4];
            af[3] = Pu[rb + ku + tq + 4];
#pragma unroll
            for (int f = 0; f < 16; ++f) {
                int c36 = (f * 8 + g) * 36;
                uint32_t bf[2];
                bf[0] = Vu[c36 + ku + tq];
                bf[1] = Vu[c36 + ku + tq + 4];
                mma_f16(o[f], af, bf);
            }
        }
    }

    // epilogue -> g_attn (fp16)
    float i0 = 1.f / l0, i1 = 1.f / l1;
    int b = bh >> 4, h = bh & 15;
    __half* base0 = g_attn + ((size_t)(b * SS + r0)) * HID + h * DD;
    __half* base1 = g_attn + ((size_t)(b * SS + r1)) * HID + h * DD;
#pragma unroll
    for (int f = 0; f < 16; ++f) {
        int c = f * 8 + 2 * tq;
        *(__half2*)(base0 + c) = __floats2half2_rn(o[f][0] * i0, o[f][1] * i0);
        *(__half2*)(base1 + c) = __floats2half2_rn(o[f][2] * i1, o[f][3] * i1);
    }
}

// ---------------------------------------------------------------------------
extern "C" void kernel_launch(void* const* d_in, const int* in_sizes, int n_in,
                              void* d_out, int out_size) {
    const float* x     = (const float*)d_in[0];
    const float* w_qkv = (const float*)d_in[1];
    const float* w_o   = (const float*)d_in[2];
    float* out = (float*)d_out;

    cudaFuncSetAttribute(mma_gemm<0>, cudaFuncAttributeMaxDynamicSharedMemorySize,
                         GEMM_SMEM);
    cudaFuncSetAttribute(mma_gemm<1>, cudaFuncAttributeMaxDynamicSharedMemorySize,
                         GEMM_SMEM);
    cudaFuncSetAttribute(flash_kernel, cudaFuncAttributeMaxDynamicSharedMemorySize,
                         FL4_SMEM_BYTES);

    // 0. Convert GEMM inputs to fp16
    preround_kernel<<<(unsigned)((NTOT4 + 255) / 256), 256>>>(x, w_qkv, w_o);

    // 1. QKV projection -> g_q/g_k (b,h,s,d), g_v (b,h,d,s)
    dim3 g1(N1 / NT, MROWS / MT);
    mma_gemm<0><<<g1, 256, GEMM_SMEM>>>(nullptr);

    // 2. RoPE in-place on q,k
    rope_kernel<<<(BB * HH * SS * 64) / 256, 256>>>();

    // 3. Flash attention (fp16 mma) -> g_attn
    flash_kernel<<<dim3(SS / 128, BB * HH), 256, FL4_SMEM_BYTES>>>();

    // 4. Output projection -> d_out (fp32)
    dim3 g2(N2 / NT, MROWS / MT);
    mma_gemm<1><<<g2, 256, GEMM_SMEM>>>(out);
}

// round 11
// speedup vs baseline: 35.4153x; 1.0434x over previous
#include <cuda_runtime.h>
#include <cuda_fp16.h>
#include <cstdint>
#include <math.h>

// Problem constants
#define BB   2
#define SS   2048
#define HH   16
#define DD   128
#define HID  2048
#define MROWS 4096          // B*S
#define KDIM  2048
#define N1    6144          // 3*HID
#define N2    2048
#define SCALE 0.08838834764831843f

// Scratch (allocation-free: __device__ globals) — fp16
__device__ __half g_q[BB*HH*SS*DD];            // (b,h,s,d)
__device__ __half g_k[BB*HH*SS*DD];            // (b,h,s,d)
__device__ __half g_v[BB*HH*SS*DD];            // (b,h,d,s)  TRANSPOSED
__device__ __half g_attn[(size_t)MROWS*HID];   // (b,s,hid)
__device__ __half g_xr[(size_t)MROWS*KDIM];
__device__ __half g_wq[(size_t)N1*KDIM];
__device__ __half g_wo[(size_t)N2*KDIM];

// ---------------------------------------------------------------------------
// Helpers
// ---------------------------------------------------------------------------
__device__ __forceinline__ void cp_async16(uint32_t dst, const void* src) {
    asm volatile("cp.async.cg.shared.global [%0], [%1], 16;" :: "r"(dst), "l"(src));
}
__device__ __forceinline__ uint32_t smem_u32(const void* p) {
    uint32_t a;
    asm("{ .reg .u64 t; cvta.to.shared.u64 t, %1; cvt.u32.u64 %0, t; }"
        : "=r"(a) : "l"(p));
    return a;
}
// D += A*B : m16n8k16 f16 (row.col), fp32 accumulate
__device__ __forceinline__ void mma_f16(float* d, const uint32_t* a, const uint32_t* b) {
    asm volatile(
        "mma.sync.aligned.m16n8k16.row.col.f32.f16.f16.f32 "
        "{%0,%1,%2,%3}, {%4,%5,%6,%7}, {%8,%9}, {%0,%1,%2,%3};"
        : "+f"(d[0]), "+f"(d[1]), "+f"(d[2]), "+f"(d[3])
        : "r"(a[0]), "r"(a[1]), "r"(a[2]), "r"(a[3]), "r"(b[0]), "r"(b[1]));
}
#define LDSM4(r0, r1, r2, r3, addr)                                            \
    asm volatile("ldmatrix.sync.aligned.m8n8.x4.shared.b16 {%0,%1,%2,%3}, [%4];" \
                 : "=r"(r0), "=r"(r1), "=r"(r2), "=r"(r3) : "r"(addr))

// ---------------------------------------------------------------------------
// Pre-round pass: x, w_qkv, w_o (fp32) -> fp16 copies.
// ---------------------------------------------------------------------------
#define NX  ((size_t)MROWS*KDIM)
#define NWQ ((size_t)N1*KDIM)
#define NWO ((size_t)N2*KDIM)
#define NTOT4 ((NX + NWQ + NWO) / 4)

__global__ __launch_bounds__(256) void preround_kernel(const float* __restrict__ x,
                                                       const float* __restrict__ wq,
                                                       const float* __restrict__ wo) {
    size_t i4 = (size_t)blockIdx.x * 256 + threadIdx.x;
    if (i4 >= NTOT4) return;
    size_t i = i4 * 4;
    const float* src;
    __half* dst;
    if (i < NX)            { src = x  + i;              dst = g_xr + i; }
    else if (i < NX + NWQ) { src = wq + (i - NX);       dst = g_wq + (i - NX); }
    else                   { src = wo + (i - NX - NWQ); dst = g_wo + (i - NX - NWQ); }
    float4 v = *(const float4*)src;
    __half2 h0 = __floats2half2_rn(v.x, v.y);
    __half2 h1 = __floats2half2_rn(v.z, v.w);
    uint2 u;
    u.x = *(uint32_t*)&h0;
    u.y = *(uint32_t*)&h1;
    *(uint2*)dst = u;
}

// ---------------------------------------------------------------------------
// fp16 mma.sync GEMM with ldmatrix operand loads.
// CTA tile 128x128, K-chunk 64 halves, 8 warps (4m x 2n), warp tile 32x64.
// ---------------------------------------------------------------------------
#define MT 128
#define NT 128
#define KCH 64
#define STRH 72
#define STG_HALVES (MT*STRH + NT*STRH)
#define GEMM_SMEM  (2 * STG_HALVES * 2)
#define GNCHUNK (KDIM / KCH)

template<int MODE>
__global__ __launch_bounds__(256) void mma_gemm(float* __restrict__ C) {
    extern __shared__ __half smh[];
    uint32_t sb = smem_u32(smh);
    int tid = threadIdx.x;
    int wid = tid >> 5;
    int lid = tid & 31;
    int g   = lid >> 2;
    int tq  = lid & 3;

    const __half* A = (MODE == 0) ? g_xr : g_attn;
    const __half* W = (MODE == 0) ? g_wq : g_wo;
    int m0 = blockIdx.y * MT;
    int n0 = blockIdx.x * NT;

    int wm = (wid & 3) * 32;
    int wn = (wid >> 2) * 64;

    // ldmatrix lane offsets
    int la  = lid & 15;                        // A row
    int lk  = (lid >> 4) << 3;                 // A k offset (halves)
    int lb  = (lid & 7) + ((lid & 16) ? 8 : 0);// B col
    int lbk = (lid & 8) ? 8 : 0;               // B k offset

    uint32_t aoff0 = ((wm + la) * STRH + lk) * 2;
    uint32_t aoff1 = aoff0 + 16 * STRH * 2;
    uint32_t boff[4];
#pragma unroll
    for (int p = 0; p < 4; ++p)
        boff[p] = (uint32_t)(MT * STRH + (wn + p * 16 + lb) * STRH + lbk) * 2;

    float acc[2][8][4];
#pragma unroll
    for (int i = 0; i < 2; ++i)
#pragma unroll
        for (int j = 0; j < 8; ++j)
#pragma unroll
            for (int q = 0; q < 4; ++q) acc[i][j][q] = 0.f;

    auto load_stage = [&](int stg, int k0) {
        uint32_t abase = sb + stg * STG_HALVES * 2;
        uint32_t bbase = abase + MT * STRH * 2;
#pragma unroll
        for (int j = 0; j < 4; ++j) {
            int ci = tid + j * 256;
            int r = ci >> 3, kc = ci & 7;
            cp_async16(abase + (r * STRH + kc * 8) * 2,
                       A + (size_t)(m0 + r) * KDIM + k0 + kc * 8);
        }
#pragma unroll
        for (int j = 0; j < 4; ++j) {
            int ci = tid + j * 256;
            int r = ci >> 3, kc = ci & 7;
            cp_async16(bbase + (r * STRH + kc * 8) * 2,
                       W + (size_t)(n0 + r) * KDIM + k0 + kc * 8);
        }
    };

    load_stage(0, 0);
    asm volatile("cp.async.commit_group;" ::: "memory");

    for (int u = 0; u < GNCHUNK; ++u) {
        if (u + 1 < GNCHUNK) {
            load_stage((u + 1) & 1, (u + 1) * KCH);
            asm volatile("cp.async.commit_group;" ::: "memory");
            asm volatile("cp.async.wait_group 1;" ::: "memory");
        } else {
            asm volatile("cp.async.wait_group 0;" ::: "memory");
        }
        __syncthreads();

        uint32_t stgbase = sb + (u & 1) * STG_HALVES * 2;

#pragma unroll
        for (int ks = 0; ks < 4; ++ks) {          // 4 k-steps of 16 halves
            uint32_t koff = ks * 32;              // bytes
            uint32_t af[2][4], bf[8][2];
            LDSM4(af[0][0], af[0][1], af[0][2], af[0][3], stgbase + aoff0 + koff);
            LDSM4(af[1][0], af[1][1], af[1][2], af[1][3], stgbase + aoff1 + koff);
#pragma unroll
            for (int p = 0; p < 4; ++p) {
                uint32_t b0, b1, b2, b3;
                LDSM4(b0, b1, b2, b3, stgbase + boff[p] + koff);
                bf[2 * p][0] = b0;     bf[2 * p][1] = b1;
                bf[2 * p + 1][0] = b2; bf[2 * p + 1][1] = b3;
            }
#pragma unroll
            for (int im = 0; im < 2; ++im)
#pragma unroll
                for (int in_ = 0; in_ < 8; ++in_)
                    mma_f16(acc[im][in_], af[im], bf[in_]);
        }
        __syncthreads();
    }

#pragma unroll
    for (int im = 0; im < 2; ++im) {
#pragma unroll
        for (int half = 0; half < 2; ++half) {
            int m = m0 + wm + im * 16 + g + half * 8;
            if (MODE == 0) {
                int qkvi = n0 >> 11;
                int rem  = n0 & 2047;
                int h = rem >> 7;
                int b = m >> 11, s = m & 2047;
                if (qkvi < 2) {
                    __half* dst = (qkvi == 0) ? g_q : g_k;
                    __half* row = dst + (((size_t)(b * HH + h)) * SS + s) * DD;
#pragma unroll
                    for (int in_ = 0; in_ < 8; ++in_) {
                        int dcol = wn + in_ * 8 + tq * 2;
                        __half2 hv = __floats2half2_rn(acc[im][in_][half * 2 + 0],
                                                       acc[im][in_][half * 2 + 1]);
                        *(__half2*)(row + dcol) = hv;
                    }
                } else {
                    __half* vb = g_v + ((size_t)(b * HH + h)) * DD * SS + s;
#pragma unroll
                    for (int in_ = 0; in_ < 8; ++in_) {
                        int dcol = wn + in_ * 8 + tq * 2;
                        vb[(size_t)dcol * SS]       = __float2half_rn(acc[im][in_][half * 2 + 0]);
                        vb[(size_t)(dcol + 1) * SS] = __float2half_rn(acc[im][in_][half * 2 + 1]);
                    }
                }
            } else {
                float* row = C + (size_t)m * N2 + n0;
#pragma unroll
                for (int in_ = 0; in_ < 8; ++in_) {
                    int dcol = wn + in_ * 8 + tq * 2;
                    float2 v;
                    v.x = acc[im][in_][half * 2 + 0];
                    v.y = acc[im][in_][half * 2 + 1];
                    *(float2*)(row + dcol) = v;
                }
            }
        }
    }
}

// ---------------------------------------------------------------------------
// RoPE in-place on g_q, g_k (fp16 storage, fp32 math).
// ---------------------------------------------------------------------------
__global__ __launch_bounds__(256) void rope_kernel() {
    int idx = blockIdx.x * 256 + threadIdx.x;
    int d   = idx & 63;
    int row = idx >> 6;
    int s   = row & (SS - 1);

    float inv = expf(-(float)d * 0.14391156831212787f);
    float ang = (float)s * inv;
    float c, sn;
    sincosf(ang, &sn, &c);

    size_t base = (size_t)row * DD;
    float q0 = __half2float(g_q[base + d]), q1 = __half2float(g_q[base + d + 64]);
    g_q[base + d]      = __float2half_rn(q0 * c - q1 * sn);
    g_q[base + d + 64] = __float2half_rn(q1 * c + q0 * sn);
    float k0 = __half2float(g_k[base + d]), k1 = __half2float(g_k[base + d + 64]);
    g_k[base + d]      = __float2half_rn(k0 * c - k1 * sn);
    g_k[base + d + 64] = __float2half_rn(k1 * c + k0 * sn);
}

// ---------------------------------------------------------------------------
// Flash attention v5 — fp16 m16n8k16 + ldmatrix operand loads.
// q-tile 128 (8 warps x 16 rows), k-tile 64. V is K-major (d rows, s cols).
// ---------------------------------------------------------------------------
#define QSTRH 136
#define VSTRH 72
#define PSTRH 72
#define FQ_H 0
#define FK_H (128*QSTRH)
#define FK_BUFH (64*QSTRH)
#define FV_H (FK_H + 2*FK_BUFH)
#define FP_H (FV_H + 128*VSTRH)
#define FL_H (FP_H + 128*PSTRH)
#define FL4_SMEM_BYTES (FL_H * 2)        // 106496

__global__ __launch_bounds__(256) void flash_kernel() {
    extern __shared__ __half smh[];
    uint32_t sb = smem_u32(smh);

    int tid = threadIdx.x;
    int wid = tid >> 5;
    int lid = tid & 31;
    int g   = lid >> 2;
    int tq  = lid & 3;
    int wm  = wid * 16;

    int bh = blockIdx.y;
    int qt = 15 - (int)blockIdx.x;
    int q0 = qt * 128;
    int ntiles = 2 * qt + 2;

    // ldmatrix lane offsets
    int la  = lid & 15;
    int lk  = (lid >> 4) << 3;
    int lb  = (lid & 7) + ((lid & 16) ? 8 : 0);
    int lbk = (lid & 8) ? 8 : 0;

    uint32_t qa_off = sb + (uint32_t)(FQ_H + (wm + la) * QSTRH + lk) * 2;
    uint32_t pa_off = sb + (uint32_t)(FP_H + (wm + la) * PSTRH + lk) * 2;
    uint32_t kb_base = sb + (uint32_t)FK_H * 2 + (uint32_t)(lb * QSTRH + lbk) * 2;
    uint32_t vb_base = sb + (uint32_t)FV_H * 2 + (uint32_t)(lb * VSTRH + lbk) * 2;

    const __half* Qg = g_q + (size_t)bh * (SS * DD);
    const __half* Kg = g_k + (size_t)bh * (SS * DD);
    const __half* Vg = g_v + (size_t)bh * (DD * SS);   // (d, s)

    // prologue: Q (128 x 128 halves) + K tile 0
#pragma unroll
    for (int j = 0; j < 8; ++j) {
        int ci = tid + j * 256;
        int r = ci >> 4, kc = ci & 15;
        cp_async16(sb + (FQ_H + r * QSTRH + kc * 8) * 2,
                   Qg + (size_t)(q0 + r) * DD + kc * 8);
    }
#pragma unroll
    for (int j = 0; j < 4; ++j) {
        int ci = tid + j * 256;
        int r = ci >> 4, kc = ci & 15;
        cp_async16(sb + (FK_H + r * QSTRH + kc * 8) * 2,
                   Kg + (size_t)r * DD + kc * 8);
    }
    asm volatile("cp.async.commit_group;" ::: "memory");

    int r0 = q0 + wm + g;
    int r1 = r0 + 8;

    float mx0 = -1e30f, mx1 = -1e30f, l0 = 0.f, l1 = 0.f;
    float o[16][4];
#pragma unroll
    for (int f = 0; f < 16; ++f)
#pragma unroll
        for (int q = 0; q < 4; ++q) o[f][q] = 0.f;

    for (int jt = 0; jt < ntiles; ++jt) {
        int kbase = jt * 64;
        bool haveNext = (jt + 1 < ntiles);
        if (jt > 0) __syncthreads();

        // prefetch V[jt] (128 d-rows x 64 s-halves) and K[jt+1]
#pragma unroll
        for (int j = 0; j < 4; ++j) {
            int ci = tid + j * 256;
            int r = ci >> 3, kc = ci & 7;
            cp_async16(sb + (FV_H + r * VSTRH + kc * 8) * 2,
                       Vg + (size_t)r * SS + kbase + kc * 8);
        }
        asm volatile("cp.async.commit_group;" ::: "memory");
        if (haveNext) {
            int nb = (jt + 1) & 1;
#pragma unroll
            for (int j = 0; j < 4; ++j) {
                int ci = tid + j * 256;
                int r = ci >> 4, kc = ci & 15;
                cp_async16(sb + (FK_H + nb * FK_BUFH + r * QSTRH + kc * 8) * 2,
                           Kg + (size_t)(kbase + 64 + r) * DD + kc * 8);
            }
            asm volatile("cp.async.commit_group;" ::: "memory");
            asm volatile("cp.async.wait_group 2;" ::: "memory");
        } else {
            asm volatile("cp.async.wait_group 1;" ::: "memory");
        }
        __syncthreads();

        // ---- S = Q K^T : 8 k-steps of 16, 8 n-frags
        uint32_t kb = kb_base + ((jt & 1) ? FK_BUFH * 2 : 0);
        float s[8][4];
#pragma unroll
        for (int f = 0; f < 8; ++f)
#pragma unroll
            for (int q = 0; q < 4; ++q) s[f][q] = 0.f;

#pragma unroll
        for (int ks = 0; ks < 8; ++ks) {
            uint32_t koff = ks * 32;
            uint32_t af[4], bf[8][2];
            LDSM4(af[0], af[1], af[2], af[3], qa_off + koff);
#pragma unroll
            for (int p = 0; p < 4; ++p) {
                uint32_t b0, b1, b2, b3;
                LDSM4(b0, b1, b2, b3, kb + p * 16 * QSTRH * 2 + koff);
                bf[2 * p][0] = b0;     bf[2 * p][1] = b1;
                bf[2 * p + 1][0] = b2; bf[2 * p + 1][1] = b3;
            }
#pragma unroll
            for (int f = 0; f < 8; ++f)
                mma_f16(s[f], af, bf[f]);
        }

        if (haveNext) asm volatile("cp.async.wait_group 1;" ::: "memory");
        else          asm volatile("cp.async.wait_group 0;" ::: "memory");
        __syncthreads();

        // ---- online softmax
        bool diag = (jt >= 2 * qt);
        float tm0 = -1e30f, tm1 = -1e30f;
#pragma unroll
        for (int f = 0; f < 8; ++f) {
            float v0 = s[f][0] * SCALE, v1 = s[f][1] * SCALE;
            float v2 = s[f][2] * SCALE, v3 = s[f][3] * SCALE;
            if (diag) {
                int c0 = kbase + f * 8 + 2 * tq, c1 = c0 + 1;
                if (c0 > r0) v0 = -1e30f;
                if (c1 > r0) v1 = -1e30f;
                if (c0 > r1) v2 = -1e30f;
                if (c1 > r1) v3 = -1e30f;
            }
            s[f][0] = v0; s[f][1] = v1; s[f][2] = v2; s[f][3] = v3;
            tm0 = fmaxf(tm0, fmaxf(v0, v1));
            tm1 = fmaxf(tm1, fmaxf(v2, v3));
        }
        tm0 = fmaxf(tm0, __shfl_xor_sync(0xffffffffu, tm0, 1));
        tm0 = fmaxf(tm0, __shfl_xor_sync(0xffffffffu, tm0, 2));
        tm1 = fmaxf(tm1, __shfl_xor_sync(0xffffffffu, tm1, 1));
        tm1 = fmaxf(tm1, __shfl_xor_sync(0xffffffffu, tm1, 2));
        float mn0 = fmaxf(mx0, tm0), mn1 = fmaxf(mx1, tm1);

        __half2* Ph = (__half2*)smh;
        float ps0 = 0.f, ps1 = 0.f;
#pragma unroll
        for (int f = 0; f < 8; ++f) {
            float p0 = __expf(s[f][0] - mn0);
            float p1 = __expf(s[f][1] - mn0);
            float p2 = __expf(s[f][2] - mn1);
            float p3 = __expf(s[f][3] - mn1);
            __half2 h01 = __floats2half2_rn(p0, p1);
            __half2 h23 = __floats2half2_rn(p2, p3);
            float2 f01 = __half22float2(h01);
            float2 f23 = __half22float2(h23);
            ps0 += f01.x + f01.y;
            ps1 += f23.x + f23.y;
            int i0 = (FP_H >> 1) + (wm + g) * 36 + f * 4 + tq;
            int i1 = (FP_H >> 1) + (wm + 8 + g) * 36 + f * 4 + tq;
            Ph[i0] = h01;
            Ph[i1] = h23;
        }
        ps0 += __shfl_xor_sync(0xffffffffu, ps0, 1);
        ps0 += __shfl_xor_sync(0xffffffffu, ps0, 2);
        ps1 += __shfl_xor_sync(0xffffffffu, ps1, 1);
        ps1 += __shfl_xor_sync(0xffffffffu, ps1, 2);

        float a0 = __expf(mx0 - mn0), a1 = __expf(mx1 - mn1);
        l0 = l0 * a0 + ps0;
        l1 = l1 * a1 + ps1;
        mx0 = mn0; mx1 = mn1;
#pragma unroll
        for (int f = 0; f < 16; ++f) {
            o[f][0] *= a0; o[f][1] *= a0;
            o[f][2] *= a1; o[f][3] *= a1;
        }
        __syncthreads();

        // ---- O += P V : 4 k-steps of 16, 16 n-frags
#pragma unroll
        for (int ks = 0; ks < 4; ++ks) {
            uint32_t koff = ks * 32;
            uint32_t af[4], bf[16][2];
            LDSM4(af[0], af[1], af[2], af[3], pa_off + koff);
#pragma unroll
            for (int p = 0; p < 8; ++p) {
                uint32_t b0, b1, b2, b3;
                LDSM4(b0, b1, b2, b3, vb_base + p * 16 * VSTRH * 2 + koff);
                bf[2 * p][0] = b0;     bf[2 * p][1] = b1;
                bf[2 * p + 1][0] = b2; bf[2 * p + 1][1] = b3;
            }
#pragma unroll
            for (int f = 0; f < 16; ++f)
                mma_f16(o[f], af, bf[f]);
        }
    }

    // epilogue -> g_attn (fp16)
    float i0 = 1.f / l0, i1 = 1.f / l1;
    int b = bh >> 4, h = bh & 15;
    __half* base0 = g_attn + ((size_t)(b * SS + r0)) * HID + h * DD;
    __half* base1 = g_attn + ((size_t)(b * SS + r1)) * HID + h * DD;
#pragma unroll
    for (int f = 0; f < 16; ++f) {
        int c = f * 8 + 2 * tq;
        *(__half2*)(base0 + c) = __floats2half2_rn(o[f][0] * i0, o[f][1] * i0);
        *(__half2*)(base1 + c) = __floats2half2_rn(o[f][2] * i1, o[f][3] * i1);
    }
}

// ---------------------------------------------------------------------------
extern "C" void kernel_launch(void* const* d_in, const int* in_sizes, int n_in,
                              void* d_out, int out_size) {
    const float* x     = (const float*)d_in[0];
    const float* w_qkv = (const float*)d_in[1];
    const float* w_o   = (const float*)d_in[2];
    float* out = (float*)d_out;

    cudaFuncSetAttribute(mma_gemm<0>, cudaFuncAttributeMaxDynamicSharedMemorySize,
                         GEMM_SMEM);
    cudaFuncSetAttribute(mma_gemm<1>, cudaFuncAttributeMaxDynamicSharedMemorySize,
                         GEMM_SMEM);
    cudaFuncSetAttribute(flash_kernel, cudaFuncAttributeMaxDynamicSharedMemorySize,
                         FL4_SMEM_BYTES);

    // 0. Convert GEMM inputs to fp16
    preround_kernel<<<(unsigned)((NTOT4 + 255) / 256), 256>>>(x, w_qkv, w_o);

    // 1. QKV projection -> g_q/g_k (b,h,s,d), g_v (b,h,d,s)
    dim3 g1(N1 / NT, MROWS / MT);
    mma_gemm<0><<<g1, 256, GEMM_SMEM>>>(nullptr);

    // 2. RoPE in-place on q,k
    rope_kernel<<<(BB * HH * SS * 64) / 256, 256>>>();

    // 3. Flash attention (fp16 mma + ldmatrix) -> g_attn
    flash_kernel<<<dim3(SS / 128, BB * HH), 256, FL4_SMEM_BYTES>>>();

    // 4. Output projection -> d_out (fp32)
    dim3 g2(N2 / NT, MROWS / MT);
    mma_gemm<1><<<g2, 256, GEMM_SMEM>>>(out);
}

// round 12
// speedup vs baseline: 41.1007x; 1.1605x over previous
#include <cuda_runtime.h>
#include <cuda_fp16.h>
#include <cstdint>
#include <math.h>

// Problem constants
#define BB   2
#define SS   2048
#define HH   16
#define DD   128
#define HID  2048
#define MROWS 4096          // B*S
#define KDIM  2048
#define N1    6144          // 3*HID
#define N2    2048
#define SCALE 0.08838834764831843f

// Scratch (allocation-free: __device__ globals) — fp16
__device__ __half g_q[BB*HH*SS*DD];            // (b,h,s,d)
__device__ __half g_k[BB*HH*SS*DD];            // (b,h,s,d)
__device__ __half g_v[BB*HH*SS*DD];            // (b,h,s,d)
__device__ __half g_attn[(size_t)MROWS*HID];   // (b,s,hid)
__device__ __half g_xr[(size_t)MROWS*KDIM];
__device__ __half g_wq[(size_t)N1*KDIM];
__device__ __half g_wo[(size_t)N2*KDIM];

// ---------------------------------------------------------------------------
// Helpers
// ---------------------------------------------------------------------------
__device__ __forceinline__ void cp_async16(uint32_t dst, const void* src) {
    asm volatile("cp.async.cg.shared.global [%0], [%1], 16;" :: "r"(dst), "l"(src));
}
__device__ __forceinline__ uint32_t smem_u32(const void* p) {
    uint32_t a;
    asm("{ .reg .u64 t; cvta.to.shared.u64 t, %1; cvt.u32.u64 %0, t; }"
        : "=r"(a) : "l"(p));
    return a;
}
// D += A*B : m16n8k16 f16 (row.col), fp32 accumulate
__device__ __forceinline__ void mma_f16(float* d, const uint32_t* a, const uint32_t* b) {
    asm volatile(
        "mma.sync.aligned.m16n8k16.row.col.f32.f16.f16.f32 "
        "{%0,%1,%2,%3}, {%4,%5,%6,%7}, {%8,%9}, {%0,%1,%2,%3};"
        : "+f"(d[0]), "+f"(d[1]), "+f"(d[2]), "+f"(d[3])
        : "r"(a[0]), "r"(a[1]), "r"(a[2]), "r"(a[3]), "r"(b[0]), "r"(b[1]));
}
#define LDSM4(r0, r1, r2, r3, addr)                                            \
    asm volatile("ldmatrix.sync.aligned.m8n8.x4.shared.b16 {%0,%1,%2,%3}, [%4];" \
                 : "=r"(r0), "=r"(r1), "=r"(r2), "=r"(r3) : "r"(addr))
#define LDSM4T(r0, r1, r2, r3, addr)                                           \
    asm volatile("ldmatrix.sync.aligned.m8n8.x4.trans.shared.b16 {%0,%1,%2,%3}, [%4];" \
                 : "=r"(r0), "=r"(r1), "=r"(r2), "=r"(r3) : "r"(addr))

// ---------------------------------------------------------------------------
// Pre-round pass: x, w_qkv, w_o (fp32) -> fp16 copies.
// ---------------------------------------------------------------------------
#define NX  ((size_t)MROWS*KDIM)
#define NWQ ((size_t)N1*KDIM)
#define NWO ((size_t)N2*KDIM)
#define NTOT4 ((NX + NWQ + NWO) / 4)

__global__ __launch_bounds__(256) void preround_kernel(const float* __restrict__ x,
                                                       const float* __restrict__ wq,
                                                       const float* __restrict__ wo) {
    size_t i4 = (size_t)blockIdx.x * 256 + threadIdx.x;
    if (i4 >= NTOT4) return;
    size_t i = i4 * 4;
    const float* src;
    __half* dst;
    if (i < NX)            { src = x  + i;              dst = g_xr + i; }
    else if (i < NX + NWQ) { src = wq + (i - NX);       dst = g_wq + (i - NX); }
    else                   { src = wo + (i - NX - NWQ); dst = g_wo + (i - NX - NWQ); }
    float4 v = *(const float4*)src;
    __half2 h0 = __floats2half2_rn(v.x, v.y);
    __half2 h1 = __floats2half2_rn(v.z, v.w);
    uint2 u;
    u.x = *(uint32_t*)&h0;
    u.y = *(uint32_t*)&h1;
    *(uint2*)dst = u;
}

// ---------------------------------------------------------------------------
// fp16 mma.sync GEMM, 128 threads (4 warps 2m x 2n), CTA tile 64x128.
// K-chunk 64 halves, 2-stage cp.async pipeline, ldmatrix operands.
// MODE 0: A=g_xr, W=g_wq -> q/k/v all (b,h,s,d)
// MODE 1: A=g_attn, W=g_wo -> C=d_out (fp32)
// ---------------------------------------------------------------------------
#define MT 64
#define NT 128
#define KCH 64
#define STRH 72
#define STG_HALVES (MT*STRH + NT*STRH)        // 13824 halves
#define GEMM_SMEM  (2 * STG_HALVES * 2)       // 55296 bytes
#define GNCHUNK (KDIM / KCH)

template<int MODE>
__global__ __launch_bounds__(128) void mma_gemm(float* __restrict__ C) {
    extern __shared__ __half smh[];
    uint32_t sb = smem_u32(smh);
    int tid = threadIdx.x;
    int wid = tid >> 5;
    int lid = tid & 31;
    int g   = lid >> 2;
    int tq  = lid & 3;

    const __half* A = (MODE == 0) ? g_xr : g_attn;
    const __half* W = (MODE == 0) ? g_wq : g_wo;
    int m0 = blockIdx.y * MT;
    int n0 = blockIdx.x * NT;

    int wm = (wid & 1) * 32;
    int wn = (wid >> 1) * 64;

    // ldmatrix lane offsets
    int la  = lid & 15;
    int lk  = (lid >> 4) << 3;
    int lb  = (lid & 7) + ((lid & 16) ? 8 : 0);
    int lbk = (lid & 8) ? 8 : 0;

    uint32_t aoff0 = ((wm + la) * STRH + lk) * 2;
    uint32_t aoff1 = aoff0 + 16 * STRH * 2;
    uint32_t boff[4];
#pragma unroll
    for (int p = 0; p < 4; ++p)
        boff[p] = (uint32_t)(MT * STRH + (wn + p * 16 + lb) * STRH + lbk) * 2;

    float acc[2][8][4];
#pragma unroll
    for (int i = 0; i < 2; ++i)
#pragma unroll
        for (int j = 0; j < 8; ++j)
#pragma unroll
            for (int q = 0; q < 4; ++q) acc[i][j][q] = 0.f;

    auto load_stage = [&](int stg, int k0) {
        uint32_t abase = sb + stg * STG_HALVES * 2;
        uint32_t bbase = abase + MT * STRH * 2;
#pragma unroll
        for (int j = 0; j < 4; ++j) {            // A: 512 chunks
            int ci = tid + j * 128;
            int r = ci >> 3, kc = ci & 7;
            cp_async16(abase + (r * STRH + kc * 8) * 2,
                       A + (size_t)(m0 + r) * KDIM + k0 + kc * 8);
        }
#pragma unroll
        for (int j = 0; j < 8; ++j) {            // B: 1024 chunks
            int ci = tid + j * 128;
            int r = ci >> 3, kc = ci & 7;
            cp_async16(bbase + (r * STRH + kc * 8) * 2,
                       W + (size_t)(n0 + r) * KDIM + k0 + kc * 8);
        }
    };

    load_stage(0, 0);
    asm volatile("cp.async.commit_group;" ::: "memory");

    for (int u = 0; u < GNCHUNK; ++u) {
        if (u + 1 < GNCHUNK) {
            load_stage((u + 1) & 1, (u + 1) * KCH);
            asm volatile("cp.async.commit_group;" ::: "memory");
            asm volatile("cp.async.wait_group 1;" ::: "memory");
        } else {
            asm volatile("cp.async.wait_group 0;" ::: "memory");
        }
        __syncthreads();

        uint32_t stgbase = sb + (u & 1) * STG_HALVES * 2;

#pragma unroll
        for (int ks = 0; ks < 4; ++ks) {
            uint32_t koff = ks * 32;
            uint32_t af[2][4], bf[8][2];
            LDSM4(af[0][0], af[0][1], af[0][2], af[0][3], stgbase + aoff0 + koff);
            LDSM4(af[1][0], af[1][1], af[1][2], af[1][3], stgbase + aoff1 + koff);
#pragma unroll
            for (int p = 0; p < 4; ++p) {
                uint32_t b0, b1, b2, b3;
                LDSM4(b0, b1, b2, b3, stgbase + boff[p] + koff);
                bf[2 * p][0] = b0;     bf[2 * p][1] = b1;
                bf[2 * p + 1][0] = b2; bf[2 * p + 1][1] = b3;
            }
#pragma unroll
            for (int im = 0; im < 2; ++im)
#pragma unroll
                for (int in_ = 0; in_ < 8; ++in_)
                    mma_f16(acc[im][in_], af[im], bf[in_]);
        }
        __syncthreads();
    }

#pragma unroll
    for (int im = 0; im < 2; ++im) {
#pragma unroll
        for (int half = 0; half < 2; ++half) {
            int m = m0 + wm + im * 16 + g + half * 8;
            if (MODE == 0) {
                int qkvi = n0 >> 11;
                int rem  = n0 & 2047;
                int h = rem >> 7;
                int b = m >> 11, s = m & 2047;
                __half* dst = (qkvi == 0) ? g_q : ((qkvi == 1) ? g_k : g_v);
                __half* row = dst + (((size_t)(b * HH + h)) * SS + s) * DD;
#pragma unroll
                for (int in_ = 0; in_ < 8; ++in_) {
                    int dcol = wn + in_ * 8 + tq * 2;
                    __half2 hv = __floats2half2_rn(acc[im][in_][half * 2 + 0],
                                                   acc[im][in_][half * 2 + 1]);
                    *(__half2*)(row + dcol) = hv;
                }
            } else {
                float* row = C + (size_t)m * N2 + n0;
#pragma unroll
                for (int in_ = 0; in_ < 8; ++in_) {
                    int dcol = wn + in_ * 8 + tq * 2;
                    float2 v;
                    v.x = acc[im][in_][half * 2 + 0];
                    v.y = acc[im][in_][half * 2 + 1];
                    *(float2*)(row + dcol) = v;
                }
            }
        }
    }
}

// ---------------------------------------------------------------------------
// RoPE in-place on g_q, g_k (fp16 storage, fp32 math).
// ---------------------------------------------------------------------------
__global__ __launch_bounds__(256) void rope_kernel() {
    int idx = blockIdx.x * 256 + threadIdx.x;
    int d   = idx & 63;
    int row = idx >> 6;
    int s   = row & (SS - 1);

    float inv = expf(-(float)d * 0.14391156831212787f);
    float ang = (float)s * inv;
    float c, sn;
    sincosf(ang, &sn, &c);

    size_t base = (size_t)row * DD;
    float q0 = __half2float(g_q[base + d]), q1 = __half2float(g_q[base + d + 64]);
    g_q[base + d]      = __float2half_rn(q0 * c - q1 * sn);
    g_q[base + d + 64] = __float2half_rn(q1 * c + q0 * sn);
    float k0 = __half2float(g_k[base + d]), k1 = __half2float(g_k[base + d + 64]);
    g_k[base + d]      = __float2half_rn(k0 * c - k1 * sn);
    g_k[base + d + 64] = __float2half_rn(k1 * c + k0 * sn);
}

// ---------------------------------------------------------------------------
// Flash attention v6 — 128 threads (4 warps), q-tile 64, k-tile 64.
// V in natural (s,d); PV B-frags via ldmatrix.trans.
// smem halves: Q[64][136] | K 2x[64][136] | V[64][136] | P[64][72]
// 78848 bytes -> 2 CTAs/SM.
// ---------------------------------------------------------------------------
#define QSTRH 136
#define VSTRH 136
#define PSTRH 72
#define FQ_H 0
#define FK_H (64*QSTRH)                  // 8704
#define FK_BUFH (64*QSTRH)               // 8704
#define FV_H (FK_H + 2*FK_BUFH)          // 26112
#define FP_H (FV_H + 64*VSTRH)           // 34816
#define FL_H (FP_H + 64*PSTRH)           // 39424 halves
#define FL6_SMEM_BYTES (FL_H * 2)        // 78848

__global__ __launch_bounds__(128) void flash_kernel() {
    extern __shared__ __half smh[];
    uint32_t sb = smem_u32(smh);

    int tid = threadIdx.x;
    int wid = tid >> 5;
    int lid = tid & 31;
    int g   = lid >> 2;
    int tq  = lid & 3;
    int wm  = wid * 16;

    int bh = blockIdx.y;
    int qt = 31 - (int)blockIdx.x;       // heavy tiles first
    int q0 = qt * 64;
    int ntiles = qt + 1;

    // ldmatrix lane offsets
    int la  = lid & 15;
    int lk  = (lid >> 4) << 3;
    int lb  = (lid & 7) + ((lid & 16) ? 8 : 0);
    int lbk = (lid & 8) ? 8 : 0;

    uint32_t qa_off  = sb + (uint32_t)(FQ_H + (wm + la) * QSTRH + lk) * 2;
    uint32_t pa_off  = sb + (uint32_t)(FP_H + (wm + la) * PSTRH + lk) * 2;
    uint32_t kb_base = sb + (uint32_t)FK_H * 2 + (uint32_t)(lb * QSTRH + lbk) * 2;
    // V trans lanes: row = ks + (lid&15), col-group = (lid&16 ? 8 : 0)
    uint32_t vb_off  = sb + (uint32_t)(FV_H + (lid & 15) * VSTRH + ((lid & 16) ? 8 : 0)) * 2;

    const __half* Qg = g_q + (size_t)bh * (SS * DD);
    const __half* Kg = g_k + (size_t)bh * (SS * DD);
    const __half* Vg = g_v + (size_t)bh * (SS * DD);

    // prologue: Q (64 x 128 halves) + K tile 0
#pragma unroll
    for (int j = 0; j < 8; ++j) {
        int ci = tid + j * 128;          // 1024 chunks
        int r = ci >> 4, kc = ci & 15;
        cp_async16(sb + (FQ_H + r * QSTRH + kc * 8) * 2,
                   Qg + (size_t)(q0 + r) * DD + kc * 8);
    }
#pragma unroll
    for (int j = 0; j < 8; ++j) {
        int ci = tid + j * 128;
        int r = ci >> 4, kc = ci & 15;
        cp_async16(sb + (FK_H + r * QSTRH + kc * 8) * 2,
                   Kg + (size_t)r * DD + kc * 8);
    }
    asm volatile("cp.async.commit_group;" ::: "memory");

    int r0 = q0 + wm + g;
    int r1 = r0 + 8;

    float mx0 = -1e30f, mx1 = -1e30f, l0 = 0.f, l1 = 0.f;
    float o[16][4];
#pragma unroll
    for (int f = 0; f < 16; ++f)
#pragma unroll
        for (int q = 0; q < 4; ++q) o[f][q] = 0.f;

    for (int jt = 0; jt < ntiles; ++jt) {
        int kbase = jt * 64;
        bool haveNext = (jt + 1 < ntiles);
        if (jt > 0) __syncthreads();     // V/P/K-buf reuse safe

        // prefetch V[jt] then K[jt+1]
#pragma unroll
        for (int j = 0; j < 8; ++j) {
            int ci = tid + j * 128;
            int r = ci >> 4, kc = ci & 15;
            cp_async16(sb + (FV_H + r * VSTRH + kc * 8) * 2,
                       Vg + (size_t)(kbase + r) * DD + kc * 8);
        }
        asm volatile("cp.async.commit_group;" ::: "memory");
        if (haveNext) {
            int nb = (jt + 1) & 1;
#pragma unroll
            for (int j = 0; j < 8; ++j) {
                int ci = tid + j * 128;
                int r = ci >> 4, kc = ci & 15;
                cp_async16(sb + (FK_H + nb * FK_BUFH + r * QSTRH + kc * 8) * 2,
                           Kg + (size_t)(kbase + 64 + r) * DD + kc * 8);
            }
            asm volatile("cp.async.commit_group;" ::: "memory");
            asm volatile("cp.async.wait_group 2;" ::: "memory");   // K[jt] ready
        } else {
            asm volatile("cp.async.wait_group 1;" ::: "memory");
        }
        __syncthreads();

        // ---- S = Q K^T : 8 k-steps of 16, 8 n-frags
        uint32_t kb = kb_base + ((jt & 1) ? FK_BUFH * 2 : 0);
        float s[8][4];
#pragma unroll
        for (int f = 0; f < 8; ++f)
#pragma unroll
            for (int q = 0; q < 4; ++q) s[f][q] = 0.f;

#pragma unroll
        for (int ks = 0; ks < 8; ++ks) {
            uint32_t koff = ks * 32;
            uint32_t af[4], bf[8][2];
            LDSM4(af[0], af[1], af[2], af[3], qa_off + koff);
#pragma unroll
            for (int p = 0; p < 4; ++p) {
                uint32_t b0, b1, b2, b3;
                LDSM4(b0, b1, b2, b3, kb + p * 16 * QSTRH * 2 + koff);
                bf[2 * p][0] = b0;     bf[2 * p][1] = b1;
                bf[2 * p + 1][0] = b2; bf[2 * p + 1][1] = b3;
            }
#pragma unroll
            for (int f = 0; f < 8; ++f)
                mma_f16(s[f], af, bf[f]);
        }

        // V[jt] ready + visible before PV
        if (haveNext) asm volatile("cp.async.wait_group 1;" ::: "memory");
        else          asm volatile("cp.async.wait_group 0;" ::: "memory");
        __syncthreads();

        // ---- online softmax
        bool diag = (jt == qt);
        float tm0 = -1e30f, tm1 = -1e30f;
#pragma unroll
        for (int f = 0; f < 8; ++f) {
            float v0 = s[f][0] * SCALE, v1 = s[f][1] * SCALE;
            float v2 = s[f][2] * SCALE, v3 = s[f][3] * SCALE;
            if (diag) {
                int c0 = kbase + f * 8 + 2 * tq, c1 = c0 + 1;
                if (c0 > r0) v0 = -1e30f;
                if (c1 > r0) v1 = -1e30f;
                if (c0 > r1) v2 = -1e30f;
                if (c1 > r1) v3 = -1e30f;
            }
            s[f][0] = v0; s[f][1] = v1; s[f][2] = v2; s[f][3] = v3;
            tm0 = fmaxf(tm0, fmaxf(v0, v1));
            tm1 = fmaxf(tm1, fmaxf(v2, v3));
        }
        tm0 = fmaxf(tm0, __shfl_xor_sync(0xffffffffu, tm0, 1));
        tm0 = fmaxf(tm0, __shfl_xor_sync(0xffffffffu, tm0, 2));
        tm1 = fmaxf(tm1, __shfl_xor_sync(0xffffffffu, tm1, 1));
        tm1 = fmaxf(tm1, __shfl_xor_sync(0xffffffffu, tm1, 2));
        float mn0 = fmaxf(mx0, tm0), mn1 = fmaxf(mx1, tm1);

        __half2* Ph = (__half2*)smh;
        float ps0 = 0.f, ps1 = 0.f;
#pragma unroll
        for (int f = 0; f < 8; ++f) {
            float p0 = __expf(s[f][0] - mn0);
            float p1 = __expf(s[f][1] - mn0);
            float p2 = __expf(s[f][2] - mn1);
            float p3 = __expf(s[f][3] - mn1);
            __half2 h01 = __floats2half2_rn(p0, p1);
            __half2 h23 = __floats2half2_rn(p2, p3);
            float2 f01 = __half22float2(h01);
            float2 f23 = __half22float2(h23);
            ps0 += f01.x + f01.y;
            ps1 += f23.x + f23.y;
            int i0 = (FP_H >> 1) + (wm + g) * 36 + f * 4 + tq;
            int i1 = (FP_H >> 1) + (wm + 8 + g) * 36 + f * 4 + tq;
            Ph[i0] = h01;
            Ph[i1] = h23;
        }
        ps0 += __shfl_xor_sync(0xffffffffu, ps0, 1);
        ps0 += __shfl_xor_sync(0xffffffffu, ps0, 2);
        ps1 += __shfl_xor_sync(0xffffffffu, ps1, 1);
        ps1 += __shfl_xor_sync(0xffffffffu, ps1, 2);

        float a0 = __expf(mx0 - mn0), a1 = __expf(mx1 - mn1);
        l0 = l0 * a0 + ps0;
        l1 = l1 * a1 + ps1;
        mx0 = mn0; mx1 = mn1;
#pragma unroll
        for (int f = 0; f < 16; ++f) {
            o[f][0] *= a0; o[f][1] *= a0;
            o[f][2] *= a1; o[f][3] *= a1;
        }
        __syncwarp();      // P rows are warp-local: warp-level visibility suffices

        // ---- O += P V : 4 k-steps of 16, 16 n-frags; V via ldmatrix.trans
#pragma unroll
        for (int ks = 0; ks < 4; ++ks) {
            uint32_t af[4];
            LDSM4(af[0], af[1], af[2], af[3], pa_off + ks * 32);
            uint32_t vrow = vb_off + (uint32_t)(ks * 16 * VSTRH) * 2;
#pragma unroll
            for (int p = 0; p < 8; ++p) {
                uint32_t b0, b1, b2, b3;
                LDSM4T(b0, b1, b2, b3, vrow + p * 32);
                float* o0 = o[2 * p];
                float* o1 = o[2 * p + 1];
                uint32_t bf0[2] = {b0, b1};
                uint32_t bf1[2] = {b2, b3};
                mma_f16(o0, af, bf0);
                mma_f16(o1, af, bf1);
            }
        }
    }

    // epilogue -> g_attn (fp16)
    float i0 = 1.f / l0, i1 = 1.f / l1;
    int b = bh >> 4, h = bh & 15;
    __half* base0 = g_attn + ((size_t)(b * SS + r0)) * HID + h * DD;
    __half* base1 = g_attn + ((size_t)(b * SS + r1)) * HID + h * DD;
#pragma unroll
    for (int f = 0; f < 16; ++f) {
        int c = f * 8 + 2 * tq;
        *(__half2*)(base0 + c) = __floats2half2_rn(o[f][0] * i0, o[f][1] * i0);
        *(__half2*)(base1 + c) = __floats2half2_rn(o[f][2] * i1, o[f][3] * i1);
    }
}

// ---------------------------------------------------------------------------
extern "C" void kernel_launch(void* const* d_in, const int* in_sizes, int n_in,
                              void* d_out, int out_size) {
    const float* x     = (const float*)d_in[0];
    const float* w_qkv = (const float*)d_in[1];
    const float* w_o   = (const float*)d_in[2];
    float* out = (float*)d_out;

    cudaFuncSetAttribute(mma_gemm<0>, cudaFuncAttributeMaxDynamicSharedMemorySize,
                         GEMM_SMEM);
    cudaFuncSetAttribute(mma_gemm<1>, cudaFuncAttributeMaxDynamicSharedMemorySize,
                         GEMM_SMEM);
    cudaFuncSetAttribute(flash_kernel, cudaFuncAttributeMaxDynamicSharedMemorySize,
                         FL6_SMEM_BYTES);

    // 0. Convert GEMM inputs to fp16
    preround_kernel<<<(unsigned)((NTOT4 + 255) / 256), 256>>>(x, w_qkv, w_o);

    // 1. QKV projection -> g_q/g_k/g_v (b,h,s,d)
    dim3 g1(N1 / NT, MROWS / MT);
    mma_gemm<0><<<g1, 128, GEMM_SMEM>>>(nullptr);

    // 2. RoPE in-place on q,k
    rope_kernel<<<(BB * HH * SS * 64) / 256, 256>>>();

    // 3. Flash attention -> g_attn
    flash_kernel<<<dim3(SS / 64, BB * HH), 128, FL6_SMEM_BYTES>>>();

    // 4. Output projection -> d_out (fp32)
    dim3 g2(N2 / NT, MROWS / MT);
    mma_gemm<1><<<g2, 128, GEMM_SMEM>>>(out);
}

// round 14
// speedup vs baseline: 42.5683x; 1.0357x over previous
#include <cuda_runtime.h>
#include <cuda_fp16.h>
#include <cstdint>
#include <math.h>

// Problem constants
#define BB   2
#define SS   2048
#define HH   16
#define DD   128
#define HID  2048
#define MROWS 4096          // B*S
#define KDIM  2048
#define N1    6144          // 3*HID
#define N2    2048
#define SCALE 0.08838834764831843f

// Scratch (allocation-free: __device__ globals) — fp16
__device__ __half g_q[BB*HH*SS*DD];            // (b,h,s,d)
__device__ __half g_k[BB*HH*SS*DD];            // (b,h,s,d)
__device__ __half g_v[BB*HH*SS*DD];            // (b,h,s,d)
__device__ __half g_attn[(size_t)MROWS*HID];   // (b,s,hid)
__device__ __half g_xr[(size_t)MROWS*KDIM];
__device__ __half g_wq[(size_t)N1*KDIM];
__device__ __half g_wo[(size_t)N2*KDIM];

// ---------------------------------------------------------------------------
// Helpers
// ---------------------------------------------------------------------------
__device__ __forceinline__ void cp_async16(uint32_t dst, const void* src) {
    asm volatile("cp.async.cg.shared.global [%0], [%1], 16;" :: "r"(dst), "l"(src));
}
__device__ __forceinline__ uint32_t smem_u32(const void* p) {
    uint32_t a;
    asm("{ .reg .u64 t; cvta.to.shared.u64 t, %1; cvt.u32.u64 %0, t; }"
        : "=r"(a) : "l"(p));
    return a;
}
// D += A*B : m16n8k16 f16 (row.col), fp32 accumulate
__device__ __forceinline__ void mma_f16(float* d, const uint32_t* a, const uint32_t* b) {
    asm volatile(
        "mma.sync.aligned.m16n8k16.row.col.f32.f16.f16.f32 "
        "{%0,%1,%2,%3}, {%4,%5,%6,%7}, {%8,%9}, {%0,%1,%2,%3};"
        : "+f"(d[0]), "+f"(d[1]), "+f"(d[2]), "+f"(d[3])
        : "r"(a[0]), "r"(a[1]), "r"(a[2]), "r"(a[3]), "r"(b[0]), "r"(b[1]));
}
#define LDSM4(r0, r1, r2, r3, addr)                                            \
    asm volatile("ldmatrix.sync.aligned.m8n8.x4.shared.b16 {%0,%1,%2,%3}, [%4];" \
                 : "=r"(r0), "=r"(r1), "=r"(r2), "=r"(r3) : "r"(addr))
#define LDSM4T(r0, r1, r2, r3, addr)                                           \
    asm volatile("ldmatrix.sync.aligned.m8n8.x4.trans.shared.b16 {%0,%1,%2,%3}, [%4];" \
                 : "=r"(r0), "=r"(r1), "=r"(r2), "=r"(r3) : "r"(addr))

// ---------------------------------------------------------------------------
// Pre-round pass: x, w_qkv, w_o (fp32) -> fp16 copies.
// ---------------------------------------------------------------------------
#define NX  ((size_t)MROWS*KDIM)
#define NWQ ((size_t)N1*KDIM)
#define NWO ((size_t)N2*KDIM)
#define NTOT4 ((NX + NWQ + NWO) / 4)

__global__ __launch_bounds__(256) void preround_kernel(const float* __restrict__ x,
                                                       const float* __restrict__ wq,
                                                       const float* __restrict__ wo) {
    size_t i4 = (size_t)blockIdx.x * 256 + threadIdx.x;
    if (i4 >= NTOT4) return;
    size_t i = i4 * 4;
    const float* src;
    __half* dst;
    if (i < NX)            { src = x  + i;              dst = g_xr + i; }
    else if (i < NX + NWQ) { src = wq + (i - NX);       dst = g_wq + (i - NX); }
    else                   { src = wo + (i - NX - NWQ); dst = g_wo + (i - NX - NWQ); }
    float4 v = *(const float4*)src;
    __half2 h0 = __floats2half2_rn(v.x, v.y);
    __half2 h1 = __floats2half2_rn(v.z, v.w);
    uint2 u;
    u.x = *(uint32_t*)&h0;
    u.y = *(uint32_t*)&h1;
    *(uint2*)dst = u;
}

// ---------------------------------------------------------------------------
// fp16 mma.sync GEMM, 128 threads (4 warps 2m x 2n), CTA tile 64x128.
// K-chunk 64 halves, 2-stage cp.async pipeline, ldmatrix operands.
// __launch_bounds__(128,4): cap regs at 128 so 4 CTAs/SM (smem 55KB each).
// ---------------------------------------------------------------------------
#define MT 64
#define NT 128
#define KCH 64
#define STRH 72
#define STG_HALVES (MT*STRH + NT*STRH)        // 13824 halves
#define GEMM_SMEM  (2 * STG_HALVES * 2)       // 55296 bytes
#define GNCHUNK (KDIM / KCH)

template<int MODE>
__global__ __launch_bounds__(128, 4) void mma_gemm(float* __restrict__ C) {
    extern __shared__ __half smh[];
    uint32_t sb = smem_u32(smh);
    int tid = threadIdx.x;
    int wid = tid >> 5;
    int lid = tid & 31;
    int g   = lid >> 2;
    int tq  = lid & 3;

    const __half* A = (MODE == 0) ? g_xr : g_attn;
    const __half* W = (MODE == 0) ? g_wq : g_wo;
    int m0 = blockIdx.y * MT;
    int n0 = blockIdx.x * NT;

    int wm = (wid & 1) * 32;
    int wn = (wid >> 1) * 64;

    int la  = lid & 15;
    int lk  = (lid >> 4) << 3;
    int lb  = (lid & 7) + ((lid & 16) ? 8 : 0);
    int lbk = (lid & 8) ? 8 : 0;

    uint32_t aoff0 = ((wm + la) * STRH + lk) * 2;
    uint32_t aoff1 = aoff0 + 16 * STRH * 2;
    uint32_t boff[4];
#pragma unroll
    for (int p = 0; p < 4; ++p)
        boff[p] = (uint32_t)(MT * STRH + (wn + p * 16 + lb) * STRH + lbk) * 2;

    float acc[2][8][4];
#pragma unroll
    for (int i = 0; i < 2; ++i)
#pragma unroll
        for (int j = 0; j < 8; ++j)
#pragma unroll
            for (int q = 0; q < 4; ++q) acc[i][j][q] = 0.f;

    auto load_stage = [&](int stg, int k0) {
        uint32_t abase = sb + stg * STG_HALVES * 2;
        uint32_t bbase = abase + MT * STRH * 2;
#pragma unroll
        for (int j = 0; j < 4; ++j) {
            int ci = tid + j * 128;
            int r = ci >> 3, kc = ci & 7;
            cp_async16(abase + (r * STRH + kc * 8) * 2,
                       A + (size_t)(m0 + r) * KDIM + k0 + kc * 8);
        }
#pragma unroll
        for (int j = 0; j < 8; ++j) {
            int ci = tid + j * 128;
            int r = ci >> 3, kc = ci & 7;
            cp_async16(bbase + (r * STRH + kc * 8) * 2,
                       W + (size_t)(n0 + r) * KDIM + k0 + kc * 8);
        }
    };

    load_stage(0, 0);
    asm volatile("cp.async.commit_group;" ::: "memory");

    for (int u = 0; u < GNCHUNK; ++u) {
        if (u + 1 < GNCHUNK) {
            load_stage((u + 1) & 1, (u + 1) * KCH);
            asm volatile("cp.async.commit_group;" ::: "memory");
            asm volatile("cp.async.wait_group 1;" ::: "memory");
        } else {
            asm volatile("cp.async.wait_group 0;" ::: "memory");
        }
        __syncthreads();

        uint32_t stgbase = sb + (u & 1) * STG_HALVES * 2;

#pragma unroll
        for (int ks = 0; ks < 4; ++ks) {
            uint32_t koff = ks * 32;
            uint32_t af[2][4], bf[8][2];
            LDSM4(af[0][0], af[0][1], af[0][2], af[0][3], stgbase + aoff0 + koff);
            LDSM4(af[1][0], af[1][1], af[1][2], af[1][3], stgbase + aoff1 + koff);
#pragma unroll
            for (int p = 0; p < 4; ++p) {
                uint32_t b0, b1, b2, b3;
                LDSM4(b0, b1, b2, b3, stgbase + boff[p] + koff);
                bf[2 * p][0] = b0;     bf[2 * p][1] = b1;
                bf[2 * p + 1][0] = b2; bf[2 * p + 1][1] = b3;
            }
#pragma unroll
            for (int im = 0; im < 2; ++im)
#pragma unroll
                for (int in_ = 0; in_ < 8; ++in_)
                    mma_f16(acc[im][in_], af[im], bf[in_]);
        }
        __syncthreads();
    }

#pragma unroll
    for (int im = 0; im < 2; ++im) {
#pragma unroll
        for (int half = 0; half < 2; ++half) {
            int m = m0 + wm + im * 16 + g + half * 8;
            if (MODE == 0) {
                int qkvi = n0 >> 11;
                int rem  = n0 & 2047;
                int h = rem >> 7;
                int b = m >> 11, s = m & 2047;
                __half* dst = (qkvi == 0) ? g_q : ((qkvi == 1) ? g_k : g_v);
                __half* row = dst + (((size_t)(b * HH + h)) * SS + s) * DD;
#pragma unroll
                for (int in_ = 0; in_ < 8; ++in_) {
                    int dcol = wn + in_ * 8 + tq * 2;
                    __half2 hv = __floats2half2_rn(acc[im][in_][half * 2 + 0],
                                                   acc[im][in_][half * 2 + 1]);
                    *(__half2*)(row + dcol) = hv;
                }
            } else {
                float* row = C + (size_t)m * N2 + n0;
#pragma unroll
                for (int in_ = 0; in_ < 8; ++in_) {
                    int dcol = wn + in_ * 8 + tq * 2;
                    float2 v;
                    v.x = acc[im][in_][half * 2 + 0];
                    v.y = acc[im][in_][half * 2 + 1];
                    *(float2*)(row + dcol) = v;
                }
            }
        }
    }
}

// ---------------------------------------------------------------------------
// RoPE in-place on g_q, g_k (fp16 storage, fp32 math).
// ---------------------------------------------------------------------------
__global__ __launch_bounds__(256) void rope_kernel() {
    int idx = blockIdx.x * 256 + threadIdx.x;
    int d   = idx & 63;
    int row = idx >> 6;
    int s   = row & (SS - 1);

    float inv = expf(-(float)d * 0.14391156831212787f);
    float ang = (float)s * inv;
    float c, sn;
    sincosf(ang, &sn, &c);

    size_t base = (size_t)row * DD;
    float q0 = __half2float(g_q[base + d]), q1 = __half2float(g_q[base + d + 64]);
    g_q[base + d]      = __float2half_rn(q0 * c - q1 * sn);
    g_q[base + d + 64] = __float2half_rn(q1 * c + q0 * sn);
    float k0 = __half2float(g_k[base + d]), k1 = __half2float(g_k[base + d + 64]);
    g_k[base + d]      = __float2half_rn(k0 * c - k1 * sn);
    g_k[base + d + 64] = __float2half_rn(k1 * c + k0 * sn);
}

// ---------------------------------------------------------------------------
// Flash attention v7 — register-resident P (QK acc frag == PV A frag).
// 128 threads (4 warps), q-tile 64, k-tile 64. No P smem, no syncwarp.
// smem halves: Q[64][136] | K 2x[64][136] | V[64][136] = 69632 B -> 3 CTAs/SM.
// ---------------------------------------------------------------------------
#define QSTRH 136
#define VSTRH 136
#define FQ_H 0
#define FK_H (64*QSTRH)                  // 8704
#define FK_BUFH (64*QSTRH)               // 8704
#define FV_H (FK_H + 2*FK_BUFH)          // 26112
#define FL_H (FV_H + 64*VSTRH)           // 34816 halves
#define FL7_SMEM_BYTES (FL_H * 2)        // 69632

__global__ __launch_bounds__(128, 3) void flash_kernel() {
    extern __shared__ __half smh[];
    uint32_t sb = smem_u32(smh);

    int tid = threadIdx.x;
    int wid = tid >> 5;
    int lid = tid & 31;
    int g   = lid >> 2;
    int tq  = lid & 3;
    int wm  = wid * 16;

    int bh = blockIdx.y;
    int qt = 31 - (int)blockIdx.x;       // heavy tiles first
    int q0 = qt * 64;
    int ntiles = qt + 1;

    int la  = lid & 15;
    int lk  = (lid >> 4) << 3;
    int lb  = (lid & 7) + ((lid & 16) ? 8 : 0);
    int lbk = (lid & 8) ? 8 : 0;

    uint32_t qa_off  = sb + (uint32_t)(FQ_H + (wm + la) * QSTRH + lk) * 2;
    uint32_t kb_base = sb + (uint32_t)FK_H * 2 + (uint32_t)(lb * QSTRH + lbk) * 2;
    uint32_t vb_off  = sb + (uint32_t)(FV_H + (lid & 15) * VSTRH + ((lid & 16) ? 8 : 0)) * 2;

    const __half* Qg = g_q + (size_t)bh * (SS * DD);
    const __half* Kg = g_k + (size_t)bh * (SS * DD);
    const __half* Vg = g_v + (size_t)bh * (SS * DD);

    // prologue: Q (64 x 128 halves) + K tile 0
#pragma unroll
    for (int j = 0; j < 8; ++j) {
        int ci = tid + j * 128;
        int r = ci >> 4, kc = ci & 15;
        cp_async16(sb + (FQ_H + r * QSTRH + kc * 8) * 2,
                   Qg + (size_t)(q0 + r) * DD + kc * 8);
    }
#pragma unroll
    for (int j = 0; j < 8; ++j) {
        int ci = tid + j * 128;
        int r = ci >> 4, kc = ci & 15;
        cp_async16(sb + (FK_H + r * QSTRH + kc * 8) * 2,
                   Kg + (size_t)r * DD + kc * 8);
    }
    asm volatile("cp.async.commit_group;" ::: "memory");

    int r0 = q0 + wm + g;
    int r1 = r0 + 8;

    float mx0 = -1e30f, mx1 = -1e30f, l0 = 0.f, l1 = 0.f;
    float o[16][4];
#pragma unroll
    for (int f = 0; f < 16; ++f)
#pragma unroll
        for (int q = 0; q < 4; ++q) o[f][q] = 0.f;

    for (int jt = 0; jt < ntiles; ++jt) {
        int kbase = jt * 64;
        bool haveNext = (jt + 1 < ntiles);
        if (jt > 0) __syncthreads();     // V / K-buf reuse safe

        // prefetch V[jt] then K[jt+1]
#pragma unroll
        for (int j = 0; j < 8; ++j) {
            int ci = tid + j * 128;
            int r = ci >> 4, kc = ci & 15;
            cp_async16(sb + (FV_H + r * VSTRH + kc * 8) * 2,
                       Vg + (size_t)(kbase + r) * DD + kc * 8);
        }
        asm volatile("cp.async.commit_group;" ::: "memory");
        if (haveNext) {
            int nb = (jt + 1) & 1;
#pragma unroll
            for (int j = 0; j < 8; ++j) {
                int ci = tid + j * 128;
                int r = ci >> 4, kc = ci & 15;
                cp_async16(sb + (FK_H + nb * FK_BUFH + r * QSTRH + kc * 8) * 2,
                           Kg + (size_t)(kbase + 64 + r) * DD + kc * 8);
            }
            asm volatile("cp.async.commit_group;" ::: "memory");
            asm volatile("cp.async.wait_group 2;" ::: "memory");   // K[jt] ready
        } else {
            asm volatile("cp.async.wait_group 1;" ::: "memory");
        }
        __syncthreads();

        // ---- S = Q K^T : 8 k-steps of 16, 8 n-frags
        uint32_t kb = kb_base + ((jt & 1) ? FK_BUFH * 2 : 0);
        float s[8][4];
#pragma unroll
        for (int f = 0; f < 8; ++f)
#pragma unroll
            for (int q = 0; q < 4; ++q) s[f][q] = 0.f;

#pragma unroll
        for (int ks = 0; ks < 8; ++ks) {
            uint32_t koff = ks * 32;
            uint32_t af[4], bf[8][2];
            LDSM4(af[0], af[1], af[2], af[3], qa_off + koff);
#pragma unroll
            for (int p = 0; p < 4; ++p) {
                uint32_t b0, b1, b2, b3;
                LDSM4(b0, b1, b2, b3, kb + p * 16 * QSTRH * 2 + koff);
                bf[2 * p][0] = b0;     bf[2 * p][1] = b1;
                bf[2 * p + 1][0] = b2; bf[2 * p + 1][1] = b3;
            }
#pragma unroll
            for (int f = 0; f < 8; ++f)
                mma_f16(s[f], af, bf[f]);
        }

        // V[jt] ready + visible before PV
        if (haveNext) asm volatile("cp.async.wait_group 1;" ::: "memory");
        else          asm volatile("cp.async.wait_group 0;" ::: "memory");
        __syncthreads();

        // ---- online softmax (P stays in registers as packed half2)
        bool diag = (jt == qt);
        float tm0 = -1e30f, tm1 = -1e30f;
#pragma unroll
        for (int f = 0; f < 8; ++f) {
            float v0 = s[f][0] * SCALE, v1 = s[f][1] * SCALE;
            float v2 = s[f][2] * SCALE, v3 = s[f][3] * SCALE;
            if (diag) {
                int c0 = kbase + f * 8 + 2 * tq, c1 = c0 + 1;
                if (c0 > r0) v0 = -1e30f;
                if (c1 > r0) v1 = -1e30f;
                if (c0 > r1) v2 = -1e30f;
                if (c1 > r1) v3 = -1e30f;
            }
            s[f][0] = v0; s[f][1] = v1; s[f][2] = v2; s[f][3] = v3;
            tm0 = fmaxf(tm0, fmaxf(v0, v1));
            tm1 = fmaxf(tm1, fmaxf(v2, v3));
        }
        tm0 = fmaxf(tm0, __shfl_xor_sync(0xffffffffu, tm0, 1));
        tm0 = fmaxf(tm0, __shfl_xor_sync(0xffffffffu, tm0, 2));
        tm1 = fmaxf(tm1, __shfl_xor_sync(0xffffffffu, tm1, 1));
        tm1 = fmaxf(tm1, __shfl_xor_sync(0xffffffffu, tm1, 2));
        float mn0 = fmaxf(mx0, tm0), mn1 = fmaxf(mx1, tm1);

        uint32_t ph[8][2];
        float ps0 = 0.f, ps1 = 0.f;
#pragma unroll
        for (int f = 0; f < 8; ++f) {
            float p0 = __expf(s[f][0] - mn0);
            float p1 = __expf(s[f][1] - mn0);
            float p2 = __expf(s[f][2] - mn1);
            float p3 = __expf(s[f][3] - mn1);
            __half2 h01 = __floats2half2_rn(p0, p1);
            __half2 h23 = __floats2half2_rn(p2, p3);
            float2 f01 = __half22float2(h01);
            float2 f23 = __half22float2(h23);
            ps0 += f01.x + f01.y;
            ps1 += f23.x + f23.y;
            ph[f][0] = *(uint32_t*)&h01;
            ph[f][1] = *(uint32_t*)&h23;
        }
        ps0 += __shfl_xor_sync(0xffffffffu, ps0, 1);
        ps0 += __shfl_xor_sync(0xffffffffu, ps0, 2);
        ps1 += __shfl_xor_sync(0xffffffffu, ps1, 1);
        ps1 += __shfl_xor_sync(0xffffffffu, ps1, 2);

        float a0 = __expf(mx0 - mn0), a1 = __expf(mx1 - mn1);
        l0 = l0 * a0 + ps0;
        l1 = l1 * a1 + ps1;
        mx0 = mn0; mx1 = mn1;
#pragma unroll
        for (int f = 0; f < 16; ++f) {
            o[f][0] *= a0; o[f][1] *= a0;
            o[f][2] *= a1; o[f][3] *= a1;
        }

        // ---- O += P V : P from registers; V via ldmatrix.trans
#pragma unroll
        for (int ks = 0; ks < 4; ++ks) {
            uint32_t af[4];
            af[0] = ph[2 * ks][0];
            af[1] = ph[2 * ks][1];
            af[2] = ph[2 * ks + 1][0];
            af[3] = ph[2 * ks + 1][1];
            uint32_t vrow = vb_off + (uint32_t)(ks * 16 * VSTRH) * 2;
#pragma unroll
            for (int p = 0; p < 8; ++p) {
                uint32_t b0, b1, b2, b3;
                LDSM4T(b0, b1, b2, b3, vrow + p * 32);
                uint32_t bf0[2] = {b0, b1};
                uint32_t bf1[2] = {b2, b3};
                mma_f16(o[2 * p], af, bf0);
                mma_f16(o[2 * p + 1], af, bf1);
            }
        }
    }

    // epilogue -> g_attn (fp16)
    float i0 = 1.f / l0, i1 = 1.f / l1;
    int b = bh >> 4, h = bh & 15;
    __half* base0 = g_attn + ((size_t)(b * SS + r0)) * HID + h * DD;
    __half* base1 = g_attn + ((size_t)(b * SS + r1)) * HID + h * DD;
#pragma unroll
    for (int f = 0; f < 16; ++f) {
        int c = f * 8 + 2 * tq;
        *(__half2*)(base0 + c) = __floats2half2_rn(o[f][0] * i0, o[f][1] * i0);
        *(__half2*)(base1 + c) = __floats2half2_rn(o[f][2] * i1, o[f][3] * i1);
    }
}

// ---------------------------------------------------------------------------
extern "C" void kernel_launch(void* const* d_in, const int* in_sizes, int n_in,
                              void* d_out, int out_size) {
    const float* x     = (const float*)d_in[0];
    const float* w_qkv = (const float*)d_in[1];
    const float* w_o   = (const float*)d_in[2];
    float* out = (float*)d_out;

    cudaFuncSetAttribute(mma_gemm<0>, cudaFuncAttributeMaxDynamicSharedMemorySize,
                         GEMM_SMEM);
    cudaFuncSetAttribute(mma_gemm<1>, cudaFuncAttributeMaxDynamicSharedMemorySize,
                         GEMM_SMEM);
    cudaFuncSetAttribute(flash_kernel, cudaFuncAttributeMaxDynamicSharedMemorySize,
                         FL7_SMEM_BYTES);

    // 0. Convert GEMM inputs to fp16
    preround_kernel<<<(unsigned)((NTOT4 + 255) / 256), 256>>>(x, w_qkv, w_o);

    // 1. QKV projection -> g_q/g_k/g_v (b,h,s,d)
    dim3 g1(N1 / NT, MROWS / MT);
    mma_gemm<0><<<g1, 128, GEMM_SMEM>>>(nullptr);

    // 2. RoPE in-place on q,k
    rope_kernel<<<(BB * HH * SS * 64) / 256, 256>>>();

    // 3. Flash attention -> g_attn
    flash_kernel<<<dim3(SS / 64, BB * HH), 128, FL7_SMEM_BYTES>>>();

    // 4. Output projection -> d_out (fp32)
    dim3 g2(N2 / NT, MROWS / MT);
    mma_gemm<1><<<g2, 128, GEMM_SMEM>>>(out);
}